// round 12
// baseline (speedup 1.0000x reference)
#include <cuda_runtime.h>
#include <math.h>

#define BB 8
#define NN 2048
#define KK 32

// ---------------- scratch (device globals; no allocations) ----------------
__device__ float  g_big[BB*NN*NN];     // 134MB: G2 (knn) only now
__device__ int    g_idx[BB*NN*KK];
__device__ float  g_xt [BB*NN*3];
__device__ float  g_xx [BB*NN];
__device__ float  g_Wa1[3*64],  g_Wb1[3*64];
__device__ float  g_Wa2[64*64], g_Wb2[64*64];
__device__ float  g_m1t[BB*NN*64];
__device__ float  g_f1t[BB*NN*64];
__device__ float  g_feat[BB*128*NN];
__device__ float  g_cat [BB*512*NN];
__device__ float  g_xqt [BB*NN*32];
__device__ float  g_xk  [BB*32*NN];
__device__ float  g_rmax[BB*NN];
__device__ float  g_rinv[BB*NN];
__device__ float  g_tb  [BB*128*NN];
__device__ float  g_ub  [BB*128*NN];
__device__ float  g_fuse[BB*1024*NN];
__device__ float  g_gm  [BB*1024];
__device__ float  g_c0  [BB*512];
__device__ float  g_h1  [BB*512*NN];
__device__ float  g_h2  [BB*256*NN];
__device__ float  g_sum[64];
__device__ float  g_sumsq[64];
__device__ float  g_mean[1024];
__device__ float  g_rstd[1024];

// ---------------- double-float helpers ----------------
__device__ __forceinline__ void twoSum(float a, float b, float& s, float& e){
    s = __fadd_rn(a,b);
    float bb = __fsub_rn(s,a);
    e = __fadd_rn(__fsub_rn(a, __fsub_rn(s,bb)), __fsub_rn(b,bb));
}
__device__ __forceinline__ void dfMac(float& hi, float& lo, float a, float b){
    float p = __fmul_rn(a,b);
    float e = fmaf(a,b,-p);
    float s, err;
    twoSum(hi, p, s, err);
    lo = __fadd_rn(lo, __fadd_rn(err, e));
    float hi2 = __fadd_rn(s, lo);
    lo = __fsub_rn(lo, __fsub_rn(hi2, s));
    hi = hi2;
}

// ---------------- FMA-pipe exp (no MUFU), ~2ulp, x <= 0 ----------------
__device__ __forceinline__ float fast_exp(float x){
    float z  = fmaf(x, 1.442695041f, 12582912.0f);
    float nf = __fsub_rn(z, 12582912.0f);
    int   ni = (__float_as_int(z) & 0x7FFFFF) - 4194304;
    float r  = fmaf(nf, -0.693145751953125f, x);
    r = fmaf(nf, -1.42860677e-6f, r);
    float p = 1.9875691500e-4f;
    p = fmaf(p, r, 1.3981999507e-3f);
    p = fmaf(p, r, 8.3334519073e-3f);
    p = fmaf(p, r, 4.1665795894e-2f);
    p = fmaf(p, r, 1.6666665459e-1f);
    p = fmaf(p, r, 5.0000001201e-1f);
    float e = __fadd_rn(fmaf(__fmul_rn(r,r), p, r), 1.0f);
    if (ni < -126) ni = -126;
    float sc = __int_as_float((ni + 127) << 23);
    return __fmul_rn(e, sc);
}

// ---------------- cp.async helpers ----------------
__device__ __forceinline__ void cp16(void* dst, const void* src){
    unsigned s = (unsigned)__cvta_generic_to_shared(dst);
    asm volatile("cp.async.ca.shared.global [%0], [%1], 16;" :: "r"(s), "l"(src) : "memory");
}
__device__ __forceinline__ void cp8(void* dst, const void* src){
    unsigned s = (unsigned)__cvta_generic_to_shared(dst);
    asm volatile("cp.async.ca.shared.global [%0], [%1], 8;" :: "r"(s), "l"(src) : "memory");
}
__device__ __forceinline__ void cp_commit(){ asm volatile("cp.async.commit_group;" ::: "memory"); }
template<int N>
__device__ __forceinline__ void cp_wait(){ asm volatile("cp.async.wait_group %0;" :: "n"(N) : "memory"); }

// ---------------- BIG GEMM: no bounds, cp.async double-buffered ----------------
#define TBK 16
#define TBN 128

template<int RM>
__global__ void __launch_bounds__(256) bgemm_t(
    const float* __restrict__ A, int lda, long sA,
    const float* __restrict__ Bm, int ldb, long sB,
    float* __restrict__ C, int ldc, long sC,
    int M, int Nn, int Kd,
    const float* __restrict__ bias,
    const float* __restrict__ rowbias,
    const float* __restrict__ colscale,
    int transOut)
{
    const int TM = 16*RM;
    __shared__ float As[2][16*RM][20];
    __shared__ float Bs[2][TBK][132];
    int b = blockIdx.z;
    const float* Ab = A + (long)b*sA;
    const float* Bb = Bm + (long)b*sB;
    float* Cb = C + (long)b*sC;
    int m0 = blockIdx.y*TM, n0 = blockIdx.x*TBN;
    int tid = threadIdx.x;
    int tx = tid & 15, ty = tid >> 4;

    float acc[RM][8];
    #pragma unroll
    for (int i=0;i<RM;i++)
        #pragma unroll
        for (int j=0;j<8;j++) acc[i][j]=0.f;

    int KT = Kd / TBK;

    auto prefetch = [&](int kt, int buf){
        int k0 = kt*TBK;
        if (RM == 8){
            int row = tid >> 1, off = (tid & 1) * 8;
            const float* src = Ab + (long)(m0+row)*lda + k0 + off;
            cp16(&As[buf][row][off],   src);
            cp16(&As[buf][row][off+4], src+4);
        } else if (RM == 4){
            int row = tid >> 2, off = (tid & 3) * 4;
            cp16(&As[buf][row][off], Ab + (long)(m0+row)*lda + k0 + off);
        } else {
            int row = tid >> 3, off = (tid & 7) * 2;
            cp8(&As[buf][row][off], Ab + (long)(m0+row)*lda + k0 + off);
        }
        {
            int krow = tid >> 4, cseg = tid & 15;
            const float* src = Bb + (long)(k0+krow)*ldb + n0 + cseg*8;
            cp16(&Bs[buf][krow][cseg*8],   src);
            cp16(&Bs[buf][krow][cseg*8+4], src+4);
        }
    };

    prefetch(0, 0);
    cp_commit();

    for (int kt = 0; kt < KT; kt++){
        int buf = kt & 1;
        if (kt+1 < KT){
            prefetch(kt+1, (kt+1)&1);
            cp_commit();
            cp_wait<1>();
        } else {
            cp_wait<0>();
        }
        __syncthreads();
        #pragma unroll
        for (int kk = 0; kk < TBK; kk++){
            float ra[RM], rb[8];
            #pragma unroll
            for (int i=0;i<RM;i++) ra[i] = As[buf][ty*RM+i][kk];
            float4 b0 = *reinterpret_cast<const float4*>(&Bs[buf][kk][tx*8]);
            float4 b1 = *reinterpret_cast<const float4*>(&Bs[buf][kk][tx*8+4]);
            rb[0]=b0.x; rb[1]=b0.y; rb[2]=b0.z; rb[3]=b0.w;
            rb[4]=b1.x; rb[5]=b1.y; rb[6]=b1.z; rb[7]=b1.w;
            #pragma unroll
            for (int i=0;i<RM;i++)
                #pragma unroll
                for (int j=0;j<8;j++)
                    acc[i][j] = fmaf(ra[i], rb[j], acc[i][j]);
        }
        __syncthreads();
    }

    #pragma unroll
    for (int i=0;i<RM;i++){
        int row = m0 + ty*RM + i;
        float rb0 = 0.f;
        bool hasb = false;
        if (bias){    rb0 = __fadd_rn(rb0, bias[row]); hasb = true; }
        if (rowbias){ rb0 = __fadd_rn(rb0, rowbias[(long)b*M + row]); hasb = true; }
        #pragma unroll
        for (int j=0;j<8;j++){
            int col = n0 + tx*8 + j;
            float v = acc[i][j];
            if (hasb) v = __fadd_rn(v, rb0);
            if (colscale) v = __fdiv_rn(v, __fadd_rn(1e-6f, colscale[(long)b*Nn + col]));
            if (!transOut) Cb[(long)row*ldc + col] = v;
            else           Cb[(long)col*ldc + row] = v;
        }
    }
}

// ---------------- generic checked SGEMM (M=13 case) ----------------
template<int RM>
__global__ void __launch_bounds__(256) sgemm_t(
    const float* __restrict__ A, int lda, long sA,
    const float* __restrict__ Bm, int ldb, long sB,
    float* __restrict__ C, int ldc, long sC,
    int M, int Nn, int Kd,
    const float* __restrict__ bias,
    const float* __restrict__ rowbias,
    const float* __restrict__ colscale,
    int transOut)
{
    const int TM = 16*RM;
    __shared__ float As[TBK][16*RM+4];
    __shared__ float Bs[TBK][TBN+4];
    int b = blockIdx.z;
    const float* Ab = A + (long)b*sA;
    const float* Bb = Bm + (long)b*sB;
    float* Cb = C + (long)b*sC;
    int m0 = blockIdx.y*TM, n0 = blockIdx.x*TBN;
    int tid = threadIdx.x;
    int tx = tid & 15, ty = tid >> 4;

    float acc[RM][8];
    #pragma unroll
    for (int i=0;i<RM;i++)
        #pragma unroll
        for (int j=0;j<8;j++) acc[i][j]=0.f;

    const int TPR = 16/RM;
    int aRow  = tid / TPR;
    int aCol0 = (tid % TPR) * RM;
    int bRow  = tid >> 4;
    int bCol0 = (tid & 15) * 8;

    for (int k0 = 0; k0 < Kd; k0 += TBK) {
        #pragma unroll
        for (int j = 0; j < RM; j++) {
            int m = aRow, k = aCol0 + j;
            float v = 0.f;
            if (m0+m < M && k0+k < Kd) v = Ab[(long)(m0+m)*lda + k0+k];
            As[k][m] = v;
        }
        #pragma unroll
        for (int j = 0; j < 8; j++) {
            int k = bRow, n = bCol0 + j;
            float v = 0.f;
            if (k0+k < Kd && n0+n < Nn) v = Bb[(long)(k0+k)*ldb + n0+n];
            Bs[k][n] = v;
        }
        __syncthreads();
        #pragma unroll
        for (int kk = 0; kk < TBK; kk++) {
            float ra[RM], rb[8];
            #pragma unroll
            for (int i=0;i<RM;i++) ra[i] = As[kk][ty*RM+i];
            float4 b0 = *reinterpret_cast<const float4*>(&Bs[kk][tx*8]);
            float4 b1 = *reinterpret_cast<const float4*>(&Bs[kk][tx*8+4]);
            rb[0]=b0.x; rb[1]=b0.y; rb[2]=b0.z; rb[3]=b0.w;
            rb[4]=b1.x; rb[5]=b1.y; rb[6]=b1.z; rb[7]=b1.w;
            #pragma unroll
            for (int i=0;i<RM;i++)
                #pragma unroll
                for (int j=0;j<8;j++)
                    acc[i][j] = fmaf(ra[i], rb[j], acc[i][j]);
        }
        __syncthreads();
    }
    #pragma unroll
    for (int i=0;i<RM;i++){
        int row = m0 + ty*RM + i;
        if (row >= M) continue;
        float rb0 = 0.f;
        bool hasb = false;
        if (bias){    rb0 = __fadd_rn(rb0, bias[row]); hasb = true; }
        if (rowbias){ rb0 = __fadd_rn(rb0, rowbias[(long)b*M + row]); hasb = true; }
        #pragma unroll
        for (int j=0;j<8;j++){
            int col = n0 + tx*8 + j;
            if (col >= Nn) continue;
            float v = acc[i][j];
            if (hasb) v = __fadd_rn(v, rb0);
            if (colscale) v = __fdiv_rn(v, __fadd_rn(1e-6f, colscale[(long)b*Nn + col]));
            if (!transOut) Cb[(long)row*ldc + col] = v;
            else           Cb[(long)col*ldc + row] = v;
        }
    }
}

// ---------------- small helpers ----------------
__global__ void prep_w_k(const float* __restrict__ We1, const float* __restrict__ We2)
{
    int i = blockIdx.x*256 + threadIdx.x;
    if (i < 64*3){ int o=i/3, c=i-o*3;
        g_Wa1[c*64+o] = We1[o*6+c];
        g_Wb1[c*64+o] = We1[o*6+3+c];
    }
    if (i < 64*64){ int o=i>>6, c=i&63;
        g_Wa2[c*64+o] = We2[o*128+c];
        g_Wb2[c*64+o] = We2[o*128+64+c];
    }
}

__global__ void transpose3_k(const float* __restrict__ x)
{
    int b=blockIdx.y; int n=blockIdx.x*256+threadIdx.x;
    #pragma unroll
    for (int c=0;c<3;c++)
        g_xt[((long)b*NN+n)*3+c] = x[(long)b*3*NN + (long)c*NN + n];
}

__global__ void xx1_k(const float* __restrict__ x)
{
    int b=blockIdx.y; int n=blockIdx.x*256+threadIdx.x;
    float s=0.f;
    #pragma unroll
    for (int c=0;c<3;c++){
        float v = x[(long)b*3*NN+(long)c*NN+n];
        s = __fadd_rn(s, __fmul_rn(v,v));
    }
    g_xx[b*NN+n]=s;
}

__global__ void xx2_k()
{
    int b=blockIdx.y; int n=blockIdx.x*256+threadIdx.x;
    const float* p = g_feat + (long)b*128*NN + n;
    float s=0.f;
    #pragma unroll 8
    for (int c=0;c<64;c++){
        float v = p[(long)c*NN];
        s = __fadd_rn(s, __fmul_rn(v,v));
    }
    g_xx[b*NN+n]=s;
}

// ---------------- kNN C=3: direct pdist from coords (no Gram GEMM) ----------------
#define CCAP 192

__global__ void __launch_bounds__(256) topk_sel3_k()
{
    int b = blockIdx.y, n = blockIdx.x, t = threadIdx.x;
    const float* xxb = g_xx + (long)b*NN;
    __shared__ float xs3[NN*3];
    for (int i=t; i<NN*3; i+=256) xs3[i] = g_xt[(long)b*NN*3 + i];
    __syncthreads();
    float c0 = xs3[n*3+0], c1 = xs3[n*3+1], c2 = xs3[n*3+2];
    float xxn = xxb[n];
    float lv[8];
    #pragma unroll
    for (int j=0;j<8;j++){
        int m = t + j*256;
        float d0 = __fsub_rn(xs3[m*3+0], c0);
        float d1 = __fsub_rn(xs3[m*3+1], c1);
        float d2 = __fsub_rn(xs3[m*3+2], c2);
        lv[j] = -fmaf(d2,d2, fmaf(d1,d1, __fmul_rn(d0,d0)));
    }
    __shared__ float s_v[8]; __shared__ int s_i[8]; __shared__ int s_win;
    __shared__ float s_v32;
    __shared__ int   scand[CCAP];
    __shared__ int   scnt;
    __shared__ float ch[CCAP], cl[CCAP];

    for (int kk=0; kk<KK; kk++){
        float bv = -INFINITY; int bi = 1<<30;
        #pragma unroll
        for (int j=0;j<8;j++){
            int m = t + j*256;
            float v = lv[j];
            if (v > bv || (v == bv && m < bi)) { bv = v; bi = m; }
        }
        #pragma unroll
        for (int off=16; off; off>>=1){
            float ov = __shfl_down_sync(0xffffffffu, bv, off);
            int   oi = __shfl_down_sync(0xffffffffu, bi, off);
            if (ov > bv || (ov == bv && oi < bi)) { bv=ov; bi=oi; }
        }
        if ((t&31)==0){ s_v[t>>5]=bv; s_i[t>>5]=bi; }
        __syncthreads();
        if (t < 32){
            if (t < 8){ bv = s_v[t]; bi = s_i[t]; } else { bv=-INFINITY; bi=1<<30; }
            #pragma unroll
            for (int off=4; off; off>>=1){
                float ov = __shfl_down_sync(0xffffffffu, bv, off);
                int   oi = __shfl_down_sync(0xffffffffu, bi, off);
                if (ov > bv || (ov == bv && oi < bi)) { bv=ov; bi=oi; }
            }
            if (t==0){ s_win = bi; scand[kk] = bi; if (kk==KK-1) s_v32 = bv; }
        }
        __syncthreads();
        int w = s_win;
        if ((w & 255) == t) lv[w>>8] = -INFINITY;
    }
    if (t==0) scnt = KK;
    __syncthreads();
    float v32 = s_v32;

    #pragma unroll
    for (int j=0;j<8;j++){
        if (lv[j] != -INFINITY){
            int m = t + j*256;
            float marg = fmaf(2e-4f, xxn + xxb[m], 1e-6f);
            if (lv[j] >= v32 - marg){
                int p = atomicAdd(&scnt, 1);
                if (p < CCAP) scand[p] = m;
            }
        }
    }
    __syncthreads();
    int cnt = scnt < CCAP ? scnt : CCAP;

    if (t < cnt){
        int m = scand[t];
        float hi=0.f, lo=0.f;
        #pragma unroll
        for (int c=0;c<3;c++){
            float d = __fsub_rn(xs3[m*3+c], xs3[n*3+c]);
            dfMac(hi, lo, d, d);
        }
        ch[t]=hi; cl[t]=lo;
    }
    __syncthreads();

    if (t < cnt){
        int   mi = scand[t];
        float hi = ch[t], li = cl[t];
        int r = 0;
        for (int j=0;j<cnt;j++){
            float hj = ch[j], lj = cl[j];
            int   mj = scand[j];
            bool less = (hj < hi) || (hj == hi && (lj < li || (lj == li && mj < mi)));
            r += less;
        }
        if (r < KK) g_idx[((long)b*NN+n)*KK + r] = mi;
    }
}

// ---------------- kNN C=64: fp32 Gram top-32 + margin + exact re-rank ----------------
template<int C>
__global__ void __launch_bounds__(256) topk_sel_t(const float* __restrict__ src)
{
    int b = blockIdx.y, n = blockIdx.x, t = threadIdx.x;
    const float* row = g_big + ((long)b*NN + n)*NN;
    const float* xxb = g_xx + (long)b*NN;
    float xxn = xxb[n];
    float lv[8];
    #pragma unroll
    for (int j=0;j<8;j++){
        int m = t + j*256;
        lv[j] = 2.f*row[m] - xxn - xxb[m];
    }
    __shared__ float s_v[8]; __shared__ int s_i[8]; __shared__ int s_win;
    __shared__ float s_v32;
    __shared__ int   scand[CCAP];
    __shared__ int   scnt;
    __shared__ float ch[CCAP], cl[CCAP];
    __shared__ float cen[C];

    for (int kk=0; kk<KK; kk++){
        float bv = -INFINITY; int bi = 1<<30;
        #pragma unroll
        for (int j=0;j<8;j++){
            int m = t + j*256;
            float v = lv[j];
            if (v > bv || (v == bv && m < bi)) { bv = v; bi = m; }
        }
        #pragma unroll
        for (int off=16; off; off>>=1){
            float ov = __shfl_down_sync(0xffffffffu, bv, off);
            int   oi = __shfl_down_sync(0xffffffffu, bi, off);
            if (ov > bv || (ov == bv && oi < bi)) { bv=ov; bi=oi; }
        }
        if ((t&31)==0){ s_v[t>>5]=bv; s_i[t>>5]=bi; }
        __syncthreads();
        if (t < 32){
            if (t < 8){ bv = s_v[t]; bi = s_i[t]; } else { bv=-INFINITY; bi=1<<30; }
            #pragma unroll
            for (int off=4; off; off>>=1){
                float ov = __shfl_down_sync(0xffffffffu, bv, off);
                int   oi = __shfl_down_sync(0xffffffffu, bi, off);
                if (ov > bv || (ov == bv && oi < bi)) { bv=ov; bi=oi; }
            }
            if (t==0){ s_win = bi; scand[kk] = bi; if (kk==KK-1) s_v32 = bv; }
        }
        __syncthreads();
        int w = s_win;
        if ((w & 255) == t) lv[w>>8] = -INFINITY;
    }
    if (t==0) scnt = KK;
    __syncthreads();
    float v32 = s_v32;

    #pragma unroll
    for (int j=0;j<8;j++){
        if (lv[j] != -INFINITY){
            int m = t + j*256;
            float marg = fmaf(2e-4f, xxn + xxb[m], 1e-6f);
            if (lv[j] >= v32 - marg){
                int p = atomicAdd(&scnt, 1);
                if (p < CCAP) scand[p] = m;
            }
        }
    }
    if (t < C) cen[t] = src[((long)b*NN+n)*C + t];
    __syncthreads();
    int cnt = scnt < CCAP ? scnt : CCAP;

    if (t < cnt){
        int m = scand[t];
        const float* fm = src + ((long)b*NN+m)*C;
        float hi=0.f, lo=0.f;
        #pragma unroll 4
        for (int c=0;c<C;c++){
            float d = __fsub_rn(fm[c], cen[c]);
            dfMac(hi, lo, d, d);
        }
        ch[t]=hi; cl[t]=lo;
    }
    __syncthreads();

    if (t < cnt){
        int   mi = scand[t];
        float hi = ch[t], li = cl[t];
        int r = 0;
        for (int j=0;j<cnt;j++){
            float hj = ch[j], lj = cl[j];
            int   mj = scand[j];
            bool less = (hj < hi) || (hj == hi && (lj < li || (lj == li && mj < mi)));
            r += less;
        }
        if (r < KK) g_idx[((long)b*NN+n)*KK + r] = mi;
    }
}

// ---------------- EdgeConv: fused e + max-over-k + one-pass stats ----------------
template<int C>
__global__ void __launch_bounds__(256) ec_pass_t(
    const float* __restrict__ src,
    const float* __restrict__ Wa,
    const float* __restrict__ Wb,
    const float* __restrict__ be)
{
    int b = blockIdx.y, n = blockIdx.x, t = threadIdx.x;
    __shared__ int   sidx[KK];
    __shared__ float cen[C];
    __shared__ float Was[C*64];
    __shared__ float Wbs[C*64];
    __shared__ float dr[KK][C + (C==64 ? 1 : 0)];
    __shared__ float t1s[64];
    __shared__ float sm[256], ss[256], ss2[256];

    const float* sb = src + (long)b*NN*C;
    if (t < KK) sidx[t] = g_idx[((long)b*NN+n)*KK + t];
    if (t < C)  cen[t] = sb[(long)n*C + t];
    for (int i=t; i<C*64; i+=256){ Was[i] = Wa[i]; Wbs[i] = Wb[i]; }
    __syncthreads();

    if (t < 64){
        float a = 0.f;
        #pragma unroll
        for (int c=0;c<C;c++) a = fmaf(Wbs[c*64+t], cen[c], a);
        t1s[t] = __fadd_rn(a, be[t]);
    }
    for (int i=t; i<KK*C; i+=256){
        int k = i/C, c = i - k*C;
        dr[k][c] = __fsub_rn(sb[(long)sidx[k]*C + c], cen[c]);
    }
    __syncthreads();

    int o = t & 63, kg = t >> 6;
    float t1 = t1s[o];
    float mx = -INFINITY, s = 0.f, s2 = 0.f;
    #pragma unroll
    for (int j=0;j<8;j++){
        int k = kg*8 + j;
        float acc = 0.f;
        #pragma unroll
        for (int c=0;c<C;c++) acc = fmaf(Was[c*64+o], dr[k][c], acc);
        acc = __fadd_rn(acc, t1);
        mx = fmaxf(mx, acc);
        s += acc;
        s2 = fmaf(acc, acc, s2);
    }
    sm[t]=mx; ss[t]=s; ss2[t]=s2;
    __syncthreads();
    if (t < 128){ sm[t]=fmaxf(sm[t],sm[t+128]); ss[t]+=ss[t+128]; ss2[t]+=ss2[t+128]; }
    __syncthreads();
    if (t < 64){
        mx = fmaxf(sm[t],sm[t+64]); s = ss[t]+ss[t+64]; s2 = ss2[t]+ss2[t+64];
        g_m1t[((long)b*NN+n)*64 + t] = mx;
        atomicAdd(&g_sum[t], s);
        atomicAdd(&g_sumsq[t], s2);
    }
}

__global__ void zero_stats_k(){ int t=threadIdx.x; if (t<64){ g_sum[t]=0.f; g_sumsq[t]=0.f; } }

__global__ void ec_fin_k()
{
    int t=threadIdx.x;
    if (t<64){
        float cnt = (float)((long)BB*NN*KK);
        float m = g_sum[t]/cnt;
        float var = fmaxf(g_sumsq[t]/cnt - m*m, 0.f);
        g_mean[t]=m;
        g_rstd[t]=__fdiv_rn(1.f, __fsqrt_rn(__fadd_rn(var, 1e-5f)));
    }
}

__global__ void __launch_bounds__(256) ec_norm_k(float* __restrict__ featslice,
                                                 float* __restrict__ f1t)
{
    int b = blockIdx.y, t = threadIdx.x;
    int n = blockIdx.x*4 + (t>>6), c = t & 63;
    float v = g_m1t[((long)b*NN+n)*64 + c];
    v = fmaxf(__fmul_rn(__fsub_rn(v, g_mean[c]), g_rstd[c]), 0.f);
    featslice[(long)b*128*NN + (long)c*NN + n] = v;
    if (f1t) f1t[((long)b*NN+n)*64 + c] = v;
}

// ---------------- BN stats over [B][C][N]: deterministic two-pass, fp64 ----------------
__global__ void __launch_bounds__(256) stats_mean_k(const float* __restrict__ z, int C)
{
    int c = blockIdx.x, t = threadIdx.x;
    double s = 0.0;
    for (int i=t; i<BB*NN; i+=256){
        int b = i>>11, n = i&(NN-1);
        s += (double)z[((long)b*C + c)*NN + n];
    }
    __shared__ double sd[256];
    sd[t]=s; __syncthreads();
    for (int off=128; off; off>>=1){
        if (t<off) sd[t]+=sd[t+off];
        __syncthreads();
    }
    if (t==0) g_mean[c] = (float)(sd[0] / (double)(BB*NN));
}

__global__ void __launch_bounds__(256) stats_var_k(const float* __restrict__ z, int C)
{
    int c = blockIdx.x, t = threadIdx.x;
    float m = g_mean[c];
    double s = 0.0;
    for (int i=t; i<BB*NN; i+=256){
        int b = i>>11, n = i&(NN-1);
        float d = __fsub_rn(z[((long)b*C + c)*NN + n], m);
        s += (double)__fmul_rn(d,d);
    }
    __shared__ double sd[256];
    sd[t]=s; __syncthreads();
    for (int off=128; off; off>>=1){
        if (t<off) sd[t]+=sd[t+off];
        __syncthreads();
    }
    if (t==0){
        float var = (float)(sd[0] / (double)(BB*NN));
        g_rstd[c] = __fdiv_rn(1.f, __fsqrt_rn(__fadd_rn(var, 1e-5f)));
    }
}

__global__ void bn_relu_k(const float* __restrict__ z, float* __restrict__ o, int C)
{
    long i = (long)blockIdx.x*256 + threadIdx.x;
    int c = (int)((i>>11) & (C-1));
    float v = z[i];
    o[i] = fmaxf(__fmul_rn(__fsub_rn(v, g_mean[c]), g_rstd[c]), 0.f);
}

__global__ void bn_relu_add_k(const float* __restrict__ u, const float* __restrict__ xin,
                              long xs, float* __restrict__ o)
{
    long i = (long)blockIdx.x*256 + threadIdx.x;
    long b = i/(128L*NN); long r = i - b*128L*NN;
    int c = (int)((r>>11) & 127);
    float v = fmaxf(__fmul_rn(__fsub_rn(u[i], g_mean[c]), g_rstd[c]), 0.f);
    o[b*512L*NN + r] = __fadd_rn(xin[b*xs + r], v);
}

// ---------------- flash attention pass A: rowmax + 1/rowsum ----------------
__global__ void __launch_bounds__(256) attn_rowstats_k()
{
    int b = blockIdx.y;
    int n0 = blockIdx.x*8;
    int t = threadIdx.x, w = t>>5, lane = t&31;
    __shared__ float xqs[8][33];
    __shared__ float xks[32][132];
    {
        int n = t>>5, c = t&31;
        xqs[n][c] = g_xqt[((long)b*NN + n0+n)*32 + c];
    }
    float runmax = -INFINITY, runsum = 0.f;
    const float* xkb = g_xk + (long)b*32*NN;
    for (int mt=0; mt<16; mt++){
        __syncthreads();
        for (int i=t; i<4096; i+=256){
            int c=i>>7, m=i&127;
            xks[c][m] = xkb[(long)c*NN + mt*128 + m];
        }
        __syncthreads();
        float e[4];
        #pragma unroll
        for (int j=0;j<4;j++){
            int m = lane + j*32;
            float acc = 0.f;
            #pragma unroll
            for (int c=0;c<32;c++) acc = fmaf(xqs[w][c], xks[c][m], acc);
            e[j] = acc;
        }
        float tmax = fmaxf(fmaxf(e[0],e[1]), fmaxf(e[2],e[3]));
        #pragma unroll
        for (int off=16;off;off>>=1) tmax = fmaxf(tmax, __shfl_xor_sync(0xffffffffu,tmax,off));
        float newmax = fmaxf(runmax, tmax);
        float ts = 0.f;
        #pragma unroll
        for (int j=0;j<4;j++) ts = __fadd_rn(ts, fast_exp(__fsub_rn(e[j], newmax)));
        #pragma unroll
        for (int off=16;off;off>>=1) ts = __fadd_rn(ts, __shfl_xor_sync(0xffffffffu,ts,off));
        float f = (runmax == -INFINITY) ? 0.f : fast_exp(__fsub_rn(runmax, newmax));
        runsum = __fadd_rn(__fmul_rn(runsum, f), ts);
        runmax = newmax;
    }
    if (lane == 0){
        g_rmax[(long)b*NN + n0 + w] = runmax;
        g_rinv[(long)b*NN + n0 + w] = __fdiv_rn(1.f, runsum);
    }
}

// ---------------- flash attention pass B: tb = xin - (x@attn)/(1e-6+colsum) ----------------
__global__ void __launch_bounds__(256) attn_apply_k(const float* __restrict__ xin, long xs)
{
    int b = blockIdx.y;
    int m0 = blockIdx.x*64;
    int t = threadIdx.x;
    int tx = t&15, ty = t>>4;
    __shared__ float xq_s[32][33];
    __shared__ float xk_s[32][66];
    __shared__ float w_s[32][66];
    __shared__ float x_s[128][33];
    __shared__ float cs_s[64];
    float acc[8][4];
    #pragma unroll
    for (int i=0;i<8;i++)
        #pragma unroll
        for (int j=0;j<4;j++) acc[i][j]=0.f;
    float cacc = 0.f;
    const float* xib = xin + (long)b*xs;
    const float* xkb = g_xk + (long)b*32*NN;
    const float* rmax = g_rmax + (long)b*NN;
    const float* rinv = g_rinv + (long)b*NN;

    for (int nt=0; nt<64; nt++){
        int nbase = nt*32;
        __syncthreads();
        for (int i=t;i<1024;i+=256){ int n=i>>5,c=i&31; xq_s[n][c]=g_xqt[((long)b*NN+nbase+n)*32+c]; }
        for (int i=t;i<2048;i+=256){ int c=i>>6,m=i&63; xk_s[c][m]=xkb[(long)c*NN+m0+m]; }
        for (int i=t;i<4096;i+=256){ int r=i>>5,n=i&31; x_s[r][n]=xib[(long)r*NN+nbase+n]; }
        __syncthreads();
        #pragma unroll
        for (int i2=0;i2<8;i2++){
            int lin = t + i2*256;
            int n = lin>>6, m = lin&63;
            float e=0.f;
            #pragma unroll
            for (int c=0;c<32;c++) e = fmaf(xq_s[n][c], xk_s[c][m], e);
            w_s[n][m] = __fmul_rn(fast_exp(__fsub_rn(e, rmax[nbase+n])), rinv[nbase+n]);
        }
        __syncthreads();
        if (t < 64){
            #pragma unroll 8
            for (int n=0;n<32;n++) cacc = __fadd_rn(cacc, w_s[n][t]);
        }
        #pragma unroll 4
        for (int n=0;n<32;n++){
            float rb[4];
            #pragma unroll
            for (int j=0;j<4;j++) rb[j] = w_s[n][tx*4+j];
            #pragma unroll
            for (int i=0;i<8;i++){
                float a = x_s[ty*8+i][n];
                #pragma unroll
                for (int j=0;j<4;j++) acc[i][j] = fmaf(a, rb[j], acc[i][j]);
            }
        }
    }
    if (t<64) cs_s[t] = cacc;
    __syncthreads();
    float* tbb = g_tb + (long)b*128*NN;
    #pragma unroll
    for (int i=0;i<8;i++){
        int r = ty*8+i;
        #pragma unroll
        for (int j=0;j<4;j++){
            int m = tx*4+j;
            float v = __fdiv_rn(acc[i][j], __fadd_rn(1e-6f, cs_s[m]));
            tbb[(long)r*NN + m0+m] = __fsub_rn(xib[(long)r*NN + m0+m], v);
        }
    }
}

// ---------------- head ----------------
__global__ void gmax_k()
{
    int o=blockIdx.x, b=blockIdx.y, t=threadIdx.x;
    const float* p = g_fuse + ((long)b*1024 + o)*NN;
    float m=-INFINITY;
    for (int i=t;i<NN;i+=256) m=fmaxf(m,p[i]);
    __shared__ float sm[256]; sm[t]=m; __syncthreads();
    for (int off=128;off;off>>=1){ if(t<off) sm[t]=fmaxf(sm[t],sm[t+off]); __syncthreads(); }
    if (t==0) g_gm[b*1024+o]=sm[0];
}

__global__ void c0_k(const float* __restrict__ Wc1, const float* __restrict__ bc1)
{
    int o=blockIdx.x, b=blockIdx.y, t=threadIdx.x;
    float s=0.f;
    for (int c=t; c<1024; c+=256)
        s = fmaf(Wc1[(long)o*1536 + c], g_gm[b*1024+c], s);
    __shared__ float ss[256]; ss[t]=s; __syncthreads();
    for (int off=128;off;off>>=1){ if(t<off) ss[t]=__fadd_rn(ss[t],ss[t+off]); __syncthreads(); }
    if (t==0) g_c0[b*512+o]=__fadd_rn(ss[0],bc1[o]);
}

// ---------------- host ----------------
template<typename T, size_t NSZ>
static T* SP(T (&arr)[NSZ]){ void* p=nullptr; cudaGetSymbolAddress(&p, arr); return (T*)p; }

template<int RM>
static void sgemmT(const float* A,int lda,long sA,const float* B,int ldb,long sB,
                   float* C,int ldc,long sC,int M,int Nn,int Kd,
                   const float* bias,const float* rowbias,const float* colscale,int transOut)
{
    dim3 g((Nn+TBN-1)/TBN,(M+16*RM-1)/(16*RM),BB);
    sgemm_t<RM><<<g,256>>>(A,lda,sA,B,ldb,sB,C,ldc,sC,M,Nn,Kd,bias,rowbias,colscale,transOut);
}

template<int RM>
static void bgemmT(const float* A,int lda,long sA,const float* B,int ldb,long sB,
                   float* C,int ldc,long sC,int M,int Nn,int Kd,
                   const float* bias,const float* rowbias,const float* colscale,int transOut)
{
    dim3 g(Nn/TBN, M/(16*RM), BB);
    bgemm_t<RM><<<g,256>>>(A,lda,sA,B,ldb,sB,C,ldc,sC,M,Nn,Kd,bias,rowbias,colscale,transOut);
}

extern "C" void kernel_launch(void* const* d_in, const int* in_sizes, int n_in,
                              void* d_out, int out_size)
{
    const float* x   = (const float*)d_in[0];
    const float* We1 = (const float*)d_in[1];
    const float* be1 = (const float*)d_in[2];
    const float* We2 = (const float*)d_in[3];
    const float* be2 = (const float*)d_in[4];
    const float* Wq  = (const float*)d_in[5];
    const float* Wk  = (const float*)d_in[6];
    const float* Wt  = (const float*)d_in[7];
    const float* bt  = (const float*)d_in[8];
    const float* Wf  = (const float*)d_in[9];
    const float* bf  = (const float*)d_in[10];
    const float* Wc1 = (const float*)d_in[11];
    const float* bc1 = (const float*)d_in[12];
    const float* Wc2 = (const float*)d_in[13];
    const float* bc2 = (const float*)d_in[14];
    const float* Wc3 = (const float*)d_in[15];
    const float* bc3 = (const float*)d_in[16];
    float* out = (float*)d_out;

    float* big  = SP(g_big);
    float* f1t  = SP(g_f1t);
    float* feat = SP(g_feat);
    float* cat  = SP(g_cat);
    float* xqt  = SP(g_xqt);
    float* xk   = SP(g_xk);
    float* tb   = SP(g_tb);
    float* ub   = SP(g_ub);
    float* fuse = SP(g_fuse);
    float* c0   = SP(g_c0);
    float* h1   = SP(g_h1);
    float* h2   = SP(g_h2);
    float* xt   = SP(g_xt);
    float* Wa1  = SP(g_Wa1); float* Wb1 = SP(g_Wb1);
    float* Wa2  = SP(g_Wa2); float* Wb2 = SP(g_Wb2);

    // ---- weight prep ----
    prep_w_k<<<16,256>>>(We1, We2);

    // ---- EdgeConv block 1 (C=3): direct pdist, no Gram GEMM ----
    xx1_k<<<dim3(NN/256,BB),256>>>(x);
    transpose3_k<<<dim3(NN/256,BB),256>>>(x);
    topk_sel3_k<<<dim3(NN,BB),256>>>();
    zero_stats_k<<<1,64>>>();
    ec_pass_t<3><<<dim3(NN,BB),256>>>(xt, Wa1, Wb1, be1);
    ec_fin_k<<<1,64>>>();
    ec_norm_k<<<dim3(NN/4,BB),256>>>(feat, f1t);
    xx2_k<<<dim3(NN/256,BB),256>>>();

    // ---- EdgeConv block 2 (C=64) ----
    bgemmT<8>(f1t,64,64L*NN, feat,NN,128L*NN, big,NN,(long)NN*NN, NN,NN,64, 0,0,0,0); // G2
    topk_sel_t<64><<<dim3(NN,BB),256>>>(f1t);
    zero_stats_k<<<1,64>>>();
    ec_pass_t<64><<<dim3(NN,BB),256>>>(f1t, Wa2, Wb2, be2);
    ec_fin_k<<<1,64>>>();
    ec_norm_k<<<dim3(NN/4,BB),256>>>(feat + 64L*NN, (float*)0);

    // ---- 4 SA layers (flash attention, no attn materialization) ----
    for (int il=0; il<4; il++){
        const float* xin = (il==0)? feat : cat + (long)(il-1)*128*NN;
        long xs = (il==0)? 128L*NN : 512L*NN;
        bgemmT<2>(Wq+il*32*128,128,0, xin,NN,xs, xqt,32,32L*NN, 32,NN,128, 0,0,0,1);   // xq^T
        bgemmT<2>(Wk+il*32*128,128,0, xin,NN,xs, xk, NN,32L*NN, 32,NN,128, 0,0,0,0);   // xk
        attn_rowstats_k<<<dim3(NN/8,BB),256>>>();
        attn_apply_k<<<dim3(NN/64,BB),256>>>(xin, xs);                                 // tb = xin - xr
        bgemmT<4>(Wt+il*128*128,128,0, tb,NN,128L*NN, ub,NN,128L*NN, 128,NN,128, bt+il*128,0,0,0);
        stats_mean_k<<<128,256>>>(ub,128);
        stats_var_k<<<128,256>>>(ub,128);
        bn_relu_add_k<<<(BB*128*NN)/256,256>>>(ub, xin, xs, cat + (long)il*128*NN);
    }

    // ---- head ----
    bgemmT<8>(Wf,512,0, cat,NN,512L*NN, fuse,NN,1024L*NN, 1024,NN,512, bf,0,0,0);
    stats_mean_k<<<1024,256>>>(fuse,1024);
    stats_var_k<<<1024,256>>>(fuse,1024);
    bn_relu_k<<<(BB*1024*NN)/256,256>>>(fuse,fuse,1024);
    gmax_k<<<dim3(1024,BB),256>>>();
    c0_k<<<dim3(512,BB),256>>>(Wc1, bc1);
    bgemmT<8>(Wc1+1024,1536,0, cat,NN,512L*NN, h1,NN,512L*NN, 512,NN,512, 0,c0,0,0);
    stats_mean_k<<<512,256>>>(h1,512);
    stats_var_k<<<512,256>>>(h1,512);
    bn_relu_k<<<(BB*512*NN)/256,256>>>(h1,h1,512);
    bgemmT<4>(Wc2,512,0, h1,NN,512L*NN, h2,NN,256L*NN, 256,NN,512, bc2,0,0,0);
    stats_mean_k<<<256,256>>>(h2,256);
    stats_var_k<<<256,256>>>(h2,256);
    bn_relu_k<<<(BB*256*NN)/256,256>>>(h2,h2,256);
    sgemmT<1>(Wc3,256,0, h2,NN,256L*NN, out,NN,13L*NN, 13,NN,256, bc3,0,0,0);
}

// round 14
// speedup vs baseline: 1.2004x; 1.2004x over previous
#include <cuda_runtime.h>
#include <math.h>

#define BB 8
#define NN 2048
#define KK 32

// ---------------- scratch (device globals; no allocations) ----------------
__device__ float  g_big[BB*NN*NN];     // 134MB: G2 (knn) only
__device__ int    g_idx[BB*NN*KK];
__device__ float  g_xt [BB*NN*3];
__device__ float  g_xx [BB*NN];
__device__ float  g_Wa1[3*64],  g_Wb1[3*64];
__device__ float  g_Wa2[64*64], g_Wb2[64*64];
__device__ float  g_m1t[BB*NN*64];
__device__ float  g_f1t[BB*NN*64];
__device__ float  g_feat[BB*128*NN];
__device__ float  g_cat [BB*512*NN];
__device__ float  g_xqt [BB*NN*32];
__device__ float  g_xk  [BB*32*NN];
__device__ float  g_rmax[BB*NN];
__device__ float  g_rinv[BB*NN];
__device__ float  g_tb  [BB*128*NN];
__device__ float  g_ub  [BB*128*NN];
__device__ float  g_fuse[BB*1024*NN];
__device__ float  g_gm  [BB*1024];
__device__ float  g_c0  [BB*512];
__device__ float  g_h1  [BB*512*NN];
__device__ float  g_h2  [BB*256*NN];
__device__ float  g_sum[64];
__device__ float  g_sumsq[64];
__device__ float  g_mean[1024];
__device__ float  g_rstd[1024];

// ---------------- double-float helpers ----------------
__device__ __forceinline__ void twoSum(float a, float b, float& s, float& e){
    s = __fadd_rn(a,b);
    float bb = __fsub_rn(s,a);
    e = __fadd_rn(__fsub_rn(a, __fsub_rn(s,bb)), __fsub_rn(b,bb));
}
__device__ __forceinline__ void dfMac(float& hi, float& lo, float a, float b){
    float p = __fmul_rn(a,b);
    float e = fmaf(a,b,-p);
    float s, err;
    twoSum(hi, p, s, err);
    lo = __fadd_rn(lo, __fadd_rn(err, e));
    float hi2 = __fadd_rn(s, lo);
    lo = __fsub_rn(lo, __fsub_rn(hi2, s));
    hi = hi2;
}

// order-preserving float<->uint
__device__ __forceinline__ unsigned f2u(float v){
    unsigned b = __float_as_uint(v);
    return (b & 0x80000000u) ? ~b : (b | 0x80000000u);
}
__device__ __forceinline__ float u2f(unsigned u){
    unsigned b = (u & 0x80000000u) ? (u & 0x7FFFFFFFu) : ~u;
    return __uint_as_float(b);
}

// ---------------- FMA-pipe exp (no MUFU), ~2ulp, x <= 0 ----------------
__device__ __forceinline__ float fast_exp(float x){
    float z  = fmaf(x, 1.442695041f, 12582912.0f);
    float nf = __fsub_rn(z, 12582912.0f);
    int   ni = (__float_as_int(z) & 0x7FFFFF) - 4194304;
    float r  = fmaf(nf, -0.693145751953125f, x);
    r = fmaf(nf, -1.42860677e-6f, r);
    float p = 1.9875691500e-4f;
    p = fmaf(p, r, 1.3981999507e-3f);
    p = fmaf(p, r, 8.3334519073e-3f);
    p = fmaf(p, r, 4.1665795894e-2f);
    p = fmaf(p, r, 1.6666665459e-1f);
    p = fmaf(p, r, 5.0000001201e-1f);
    float e = __fadd_rn(fmaf(__fmul_rn(r,r), p, r), 1.0f);
    if (ni < -126) ni = -126;
    float sc = __int_as_float((ni + 127) << 23);
    return __fmul_rn(e, sc);
}

// ---------------- cp.async helpers ----------------
__device__ __forceinline__ void cp16(void* dst, const void* src){
    unsigned s = (unsigned)__cvta_generic_to_shared(dst);
    asm volatile("cp.async.ca.shared.global [%0], [%1], 16;" :: "r"(s), "l"(src) : "memory");
}
__device__ __forceinline__ void cp8(void* dst, const void* src){
    unsigned s = (unsigned)__cvta_generic_to_shared(dst);
    asm volatile("cp.async.ca.shared.global [%0], [%1], 8;" :: "r"(s), "l"(src) : "memory");
}
__device__ __forceinline__ void cp_commit(){ asm volatile("cp.async.commit_group;" ::: "memory"); }
template<int N>
__device__ __forceinline__ void cp_wait(){ asm volatile("cp.async.wait_group %0;" :: "n"(N) : "memory"); }

// ---------------- BIG GEMM: no bounds, cp.async double-buffered ----------------
#define TBK 16
#define TBN 128

template<int RM>
__global__ void __launch_bounds__(256) bgemm_t(
    const float* __restrict__ A, int lda, long sA,
    const float* __restrict__ Bm, int ldb, long sB,
    float* __restrict__ C, int ldc, long sC,
    int M, int Nn, int Kd,
    const float* __restrict__ bias,
    const float* __restrict__ rowbias,
    const float* __restrict__ colscale,
    int transOut)
{
    const int TM = 16*RM;
    __shared__ float As[2][16*RM][20];
    __shared__ float Bs[2][TBK][132];
    int b = blockIdx.z;
    const float* Ab = A + (long)b*sA;
    const float* Bb = Bm + (long)b*sB;
    float* Cb = C + (long)b*sC;
    int m0 = blockIdx.y*TM, n0 = blockIdx.x*TBN;
    int tid = threadIdx.x;
    int tx = tid & 15, ty = tid >> 4;

    float acc[RM][8];
    #pragma unroll
    for (int i=0;i<RM;i++)
        #pragma unroll
        for (int j=0;j<8;j++) acc[i][j]=0.f;

    int KT = Kd / TBK;

    auto prefetch = [&](int kt, int buf){
        int k0 = kt*TBK;
        if (RM == 8){
            int row = tid >> 1, off = (tid & 1) * 8;
            const float* src = Ab + (long)(m0+row)*lda + k0 + off;
            cp16(&As[buf][row][off],   src);
            cp16(&As[buf][row][off+4], src+4);
        } else if (RM == 4){
            int row = tid >> 2, off = (tid & 3) * 4;
            cp16(&As[buf][row][off], Ab + (long)(m0+row)*lda + k0 + off);
        } else {
            int row = tid >> 3, off = (tid & 7) * 2;
            cp8(&As[buf][row][off], Ab + (long)(m0+row)*lda + k0 + off);
        }
        {
            int krow = tid >> 4, cseg = tid & 15;
            const float* src = Bb + (long)(k0+krow)*ldb + n0 + cseg*8;
            cp16(&Bs[buf][krow][cseg*8],   src);
            cp16(&Bs[buf][krow][cseg*8+4], src+4);
        }
    };

    prefetch(0, 0);
    cp_commit();

    for (int kt = 0; kt < KT; kt++){
        int buf = kt & 1;
        if (kt+1 < KT){
            prefetch(kt+1, (kt+1)&1);
            cp_commit();
            cp_wait<1>();
        } else {
            cp_wait<0>();
        }
        __syncthreads();
        #pragma unroll
        for (int kk = 0; kk < TBK; kk++){
            float ra[RM], rb[8];
            #pragma unroll
            for (int i=0;i<RM;i++) ra[i] = As[buf][ty*RM+i][kk];
            float4 b0 = *reinterpret_cast<const float4*>(&Bs[buf][kk][tx*8]);
            float4 b1 = *reinterpret_cast<const float4*>(&Bs[buf][kk][tx*8+4]);
            rb[0]=b0.x; rb[1]=b0.y; rb[2]=b0.z; rb[3]=b0.w;
            rb[4]=b1.x; rb[5]=b1.y; rb[6]=b1.z; rb[7]=b1.w;
            #pragma unroll
            for (int i=0;i<RM;i++)
                #pragma unroll
                for (int j=0;j<8;j++)
                    acc[i][j] = fmaf(ra[i], rb[j], acc[i][j]);
        }
        __syncthreads();
    }

    #pragma unroll
    for (int i=0;i<RM;i++){
        int row = m0 + ty*RM + i;
        float rb0 = 0.f;
        bool hasb = false;
        if (bias){    rb0 = __fadd_rn(rb0, bias[row]); hasb = true; }
        if (rowbias){ rb0 = __fadd_rn(rb0, rowbias[(long)b*M + row]); hasb = true; }
        #pragma unroll
        for (int j=0;j<8;j++){
            int col = n0 + tx*8 + j;
            float v = acc[i][j];
            if (hasb) v = __fadd_rn(v, rb0);
            if (colscale) v = __fdiv_rn(v, __fadd_rn(1e-6f, colscale[(long)b*Nn + col]));
            if (!transOut) Cb[(long)row*ldc + col] = v;
            else           Cb[(long)col*ldc + row] = v;
        }
    }
}

// ---------------- generic checked SGEMM (M=13 case) ----------------
template<int RM>
__global__ void __launch_bounds__(256) sgemm_t(
    const float* __restrict__ A, int lda, long sA,
    const float* __restrict__ Bm, int ldb, long sB,
    float* __restrict__ C, int ldc, long sC,
    int M, int Nn, int Kd,
    const float* __restrict__ bias,
    const float* __restrict__ rowbias,
    const float* __restrict__ colscale,
    int transOut)
{
    const int TM = 16*RM;
    __shared__ float As[TBK][16*RM+4];
    __shared__ float Bs[TBK][TBN+4];
    int b = blockIdx.z;
    const float* Ab = A + (long)b*sA;
    const float* Bb = Bm + (long)b*sB;
    float* Cb = C + (long)b*sC;
    int m0 = blockIdx.y*TM, n0 = blockIdx.x*TBN;
    int tid = threadIdx.x;
    int tx = tid & 15, ty = tid >> 4;

    float acc[RM][8];
    #pragma unroll
    for (int i=0;i<RM;i++)
        #pragma unroll
        for (int j=0;j<8;j++) acc[i][j]=0.f;

    const int TPR = 16/RM;
    int aRow  = tid / TPR;
    int aCol0 = (tid % TPR) * RM;
    int bRow  = tid >> 4;
    int bCol0 = (tid & 15) * 8;

    for (int k0 = 0; k0 < Kd; k0 += TBK) {
        #pragma unroll
        for (int j = 0; j < RM; j++) {
            int m = aRow, k = aCol0 + j;
            float v = 0.f;
            if (m0+m < M && k0+k < Kd) v = Ab[(long)(m0+m)*lda + k0+k];
            As[k][m] = v;
        }
        #pragma unroll
        for (int j = 0; j < 8; j++) {
            int k = bRow, n = bCol0 + j;
            float v = 0.f;
            if (k0+k < Kd && n0+n < Nn) v = Bb[(long)(k0+k)*ldb + n0+n];
            Bs[k][n] = v;
        }
        __syncthreads();
        #pragma unroll
        for (int kk = 0; kk < TBK; kk++) {
            float ra[RM], rb[8];
            #pragma unroll
            for (int i=0;i<RM;i++) ra[i] = As[kk][ty*RM+i];
            float4 b0 = *reinterpret_cast<const float4*>(&Bs[kk][tx*8]);
            float4 b1 = *reinterpret_cast<const float4*>(&Bs[kk][tx*8+4]);
            rb[0]=b0.x; rb[1]=b0.y; rb[2]=b0.z; rb[3]=b0.w;
            rb[4]=b1.x; rb[5]=b1.y; rb[6]=b1.z; rb[7]=b1.w;
            #pragma unroll
            for (int i=0;i<RM;i++)
                #pragma unroll
                for (int j=0;j<8;j++)
                    acc[i][j] = fmaf(ra[i], rb[j], acc[i][j]);
        }
        __syncthreads();
    }
    #pragma unroll
    for (int i=0;i<RM;i++){
        int row = m0 + ty*RM + i;
        if (row >= M) continue;
        float rb0 = 0.f;
        bool hasb = false;
        if (bias){    rb0 = __fadd_rn(rb0, bias[row]); hasb = true; }
        if (rowbias){ rb0 = __fadd_rn(rb0, rowbias[(long)b*M + row]); hasb = true; }
        #pragma unroll
        for (int j=0;j<8;j++){
            int col = n0 + tx*8 + j;
            if (col >= Nn) continue;
            float v = acc[i][j];
            if (hasb) v = __fadd_rn(v, rb0);
            if (colscale) v = __fdiv_rn(v, __fadd_rn(1e-6f, colscale[(long)b*Nn + col]));
            if (!transOut) Cb[(long)row*ldc + col] = v;
            else           Cb[(long)col*ldc + row] = v;
        }
    }
}

// ---------------- small helpers ----------------
__global__ void prep_w_k(const float* __restrict__ We1, const float* __restrict__ We2)
{
    int i = blockIdx.x*256 + threadIdx.x;
    if (i < 64*3){ int o=i/3, c=i-o*3;
        g_Wa1[c*64+o] = We1[o*6+c];
        g_Wb1[c*64+o] = We1[o*6+3+c];
    }
    if (i < 64*64){ int o=i>>6, c=i&63;
        g_Wa2[c*64+o] = We2[o*128+c];
        g_Wb2[c*64+o] = We2[o*128+64+c];
    }
}

__global__ void transpose3_k(const float* __restrict__ x)
{
    int b=blockIdx.y; int n=blockIdx.x*256+threadIdx.x;
    #pragma unroll
    for (int c=0;c<3;c++)
        g_xt[((long)b*NN+n)*3+c] = x[(long)b*3*NN + (long)c*NN + n];
}

__global__ void xx1_k(const float* __restrict__ x)
{
    int b=blockIdx.y; int n=blockIdx.x*256+threadIdx.x;
    float s=0.f;
    #pragma unroll
    for (int c=0;c<3;c++){
        float v = x[(long)b*3*NN+(long)c*NN+n];
        s = __fadd_rn(s, __fmul_rn(v,v));
    }
    g_xx[b*NN+n]=s;
}

__global__ void xx2_k()
{
    int b=blockIdx.y; int n=blockIdx.x*256+threadIdx.x;
    const float* p = g_feat + (long)b*128*NN + n;
    float s=0.f;
    #pragma unroll 8
    for (int c=0;c<64;c++){
        float v = p[(long)c*NN];
        s = __fadd_rn(s, __fmul_rn(v,v));
    }
    g_xx[b*NN+n]=s;
}

// ============ histogram threshold select + exact df re-rank ============
#define CCAP 384

// C=3 fused: distances straight from coords in smem (SoA layout)
__global__ void __launch_bounds__(256) topk_sel3_k()
{
    int b = blockIdx.y, n = blockIdx.x, t = threadIdx.x;
    const float* xxb = g_xx + (long)b*NN;
    __shared__ float xs3[3*NN];            // [c][m]
    __shared__ int   hist[2048];
    __shared__ int   cs[256];
    __shared__ int   gsum[32];
    __shared__ int   s_B;
    __shared__ int   scand[CCAP];
    __shared__ int   scnt;
    __shared__ float ch[CCAP], cl[CCAP];

    for (int i=t; i<NN; i+=256){
        #pragma unroll
        for (int c=0;c<3;c++) xs3[c*NN+i] = g_xt[((long)b*NN+i)*3 + c];
    }
    for (int i=t; i<2048; i+=256) hist[i]=0;
    if (t==0) scnt = 0;
    __syncthreads();
    float c0 = xs3[n], c1 = xs3[NN+n], c2 = xs3[2*NN+n];
    float xxn = xxb[n];
    float lv[8];
    #pragma unroll
    for (int j=0;j<8;j++){
        int m = t + j*256;
        float d0 = __fsub_rn(xs3[m], c0);
        float d1 = __fsub_rn(xs3[NN+m], c1);
        float d2 = __fsub_rn(xs3[2*NN+m], c2);
        lv[j] = -fmaf(d2,d2, fmaf(d1,d1, __fmul_rn(d0,d0)));
        atomicAdd(&hist[f2u(lv[j])>>21], 1);
    }
    __syncthreads();
    {
        int s=0;
        #pragma unroll
        for (int k2=0;k2<8;k2++) s += hist[t*8+k2];
        cs[t]=s;
    }
    __syncthreads();
    if (t < 32){
        int s=0;
        #pragma unroll
        for (int k2=0;k2<8;k2++) s += cs[t*8+k2];
        gsum[t]=s;
    }
    __syncthreads();
    if (t==0){
        int run=0, g=31;
        for (; g>0; g--){ if (run+gsum[g] >= KK) break; run += gsum[g]; }
        int cch = g*8+7;
        for (; cch>0; cch--){ if (run+cs[cch] >= KK) break; run += cs[cch]; }
        int bkt = cch*8+7;
        for (; bkt>0; bkt--){ if (run+hist[bkt] >= KK) break; run += hist[bkt]; }
        s_B = bkt;
    }
    __syncthreads();
    float Tf = u2f((unsigned)s_B << 21);
    #pragma unroll
    for (int j=0;j<8;j++){
        int m = t + j*256;
        float marg = fmaf(2e-4f, xxn + xxb[m], 1e-6f);
        if (lv[j] >= __fsub_rn(Tf, marg)){
            int p = atomicAdd(&scnt, 1);
            if (p < CCAP) scand[p] = m;
        }
    }
    __syncthreads();
    int cnt = scnt < CCAP ? scnt : CCAP;

    if (t < cnt){
        int m = scand[t];
        float hi=0.f, lo=0.f;
        #pragma unroll
        for (int c=0;c<3;c++){
            float d = __fsub_rn(xs3[c*NN+m], xs3[c*NN+n]);
            dfMac(hi, lo, d, d);
        }
        ch[t]=hi; cl[t]=lo;
    }
    __syncthreads();
    if (t < cnt){
        int   mi = scand[t];
        float hi = ch[t], li = cl[t];
        int r = 0;
        for (int j=0;j<cnt;j++){
            float hj = ch[j], lj = cl[j];
            int   mj = scand[j];
            bool less = (hj < hi) || (hj == hi && (lj < li || (lj == li && mj < mi)));
            r += less;
        }
        if (r < KK) g_idx[((long)b*NN+n)*KK + r] = mi;
    }
}

// C=64: pdist from precomputed fp32 Gram in g_big
template<int C>
__global__ void __launch_bounds__(256) topk_sel_t(const float* __restrict__ src)
{
    int b = blockIdx.y, n = blockIdx.x, t = threadIdx.x;
    const float* row = g_big + ((long)b*NN + n)*NN;
    const float* xxb = g_xx + (long)b*NN;
    __shared__ int   hist[2048];
    __shared__ int   cs[256];
    __shared__ int   gsum[32];
    __shared__ int   s_B;
    __shared__ int   scand[CCAP];
    __shared__ int   scnt;
    __shared__ float ch[CCAP], cl[CCAP];
    __shared__ float cen[C];

    for (int i=t; i<2048; i+=256) hist[i]=0;
    if (t==0) scnt = 0;
    if (t < C) cen[t] = src[((long)b*NN+n)*C + t];
    __syncthreads();
    float xxn = xxb[n];
    float lv[8];
    #pragma unroll
    for (int j=0;j<8;j++){
        int m = t + j*256;
        lv[j] = 2.f*row[m] - xxn - xxb[m];
        atomicAdd(&hist[f2u(lv[j])>>21], 1);
    }
    __syncthreads();
    {
        int s=0;
        #pragma unroll
        for (int k2=0;k2<8;k2++) s += hist[t*8+k2];
        cs[t]=s;
    }
    __syncthreads();
    if (t < 32){
        int s=0;
        #pragma unroll
        for (int k2=0;k2<8;k2++) s += cs[t*8+k2];
        gsum[t]=s;
    }
    __syncthreads();
    if (t==0){
        int run=0, g=31;
        for (; g>0; g--){ if (run+gsum[g] >= KK) break; run += gsum[g]; }
        int cch = g*8+7;
        for (; cch>0; cch--){ if (run+cs[cch] >= KK) break; run += cs[cch]; }
        int bkt = cch*8+7;
        for (; bkt>0; bkt--){ if (run+hist[bkt] >= KK) break; run += hist[bkt]; }
        s_B = bkt;
    }
    __syncthreads();
    float Tf = u2f((unsigned)s_B << 21);
    #pragma unroll
    for (int j=0;j<8;j++){
        int m = t + j*256;
        float marg = fmaf(2e-4f, xxn + xxb[m], 1e-6f);
        if (lv[j] >= __fsub_rn(Tf, marg)){
            int p = atomicAdd(&scnt, 1);
            if (p < CCAP) scand[p] = m;
        }
    }
    __syncthreads();
    int cnt = scnt < CCAP ? scnt : CCAP;

    if (t < cnt){
        int m = scand[t];
        const float* fm = src + ((long)b*NN+m)*C;
        float hi=0.f, lo=0.f;
        #pragma unroll 4
        for (int c=0;c<C;c++){
            float d = __fsub_rn(fm[c], cen[c]);
            dfMac(hi, lo, d, d);
        }
        ch[t]=hi; cl[t]=lo;
    }
    __syncthreads();
    if (t < cnt){
        int   mi = scand[t];
        float hi = ch[t], li = cl[t];
        int r = 0;
        for (int j=0;j<cnt;j++){
            float hj = ch[j], lj = cl[j];
            int   mj = scand[j];
            bool less = (hj < hi) || (hj == hi && (lj < li || (lj == li && mj < mi)));
            r += less;
        }
        if (r < KK) g_idx[((long)b*NN+n)*KK + r] = mi;
    }
}

// ---------------- EdgeConv: fused e + max-over-k + one-pass stats ----------------
template<int C>
__global__ void __launch_bounds__(256) ec_pass_t(
    const float* __restrict__ src,
    const float* __restrict__ Wa,
    const float* __restrict__ Wb,
    const float* __restrict__ be)
{
    int b = blockIdx.y, n = blockIdx.x, t = threadIdx.x;
    __shared__ int   sidx[KK];
    __shared__ float cen[C];
    __shared__ float Was[C*64];
    __shared__ float Wbs[C*64];
    __shared__ float dr[KK][C + (C==64 ? 1 : 0)];
    __shared__ float t1s[64];
    __shared__ float sm[256], ss[256], ss2[256];

    const float* sb = src + (long)b*NN*C;
    if (t < KK) sidx[t] = g_idx[((long)b*NN+n)*KK + t];
    if (t < C)  cen[t] = sb[(long)n*C + t];
    for (int i=t; i<C*64; i+=256){ Was[i] = Wa[i]; Wbs[i] = Wb[i]; }
    __syncthreads();

    if (t < 64){
        float a = 0.f;
        #pragma unroll
        for (int c=0;c<C;c++) a = fmaf(Wbs[c*64+t], cen[c], a);
        t1s[t] = __fadd_rn(a, be[t]);
    }
    for (int i=t; i<KK*C; i+=256){
        int k = i/C, c = i - k*C;
        dr[k][c] = __fsub_rn(sb[(long)sidx[k]*C + c], cen[c]);
    }
    __syncthreads();

    int o = t & 63, kg = t >> 6;
    float t1 = t1s[o];
    float mx = -INFINITY, s = 0.f, s2 = 0.f;
    #pragma unroll
    for (int j=0;j<8;j++){
        int k = kg*8 + j;
        float acc = 0.f;
        #pragma unroll
        for (int c=0;c<C;c++) acc = fmaf(Was[c*64+o], dr[k][c], acc);
        acc = __fadd_rn(acc, t1);
        mx = fmaxf(mx, acc);
        s += acc;
        s2 = fmaf(acc, acc, s2);
    }
    sm[t]=mx; ss[t]=s; ss2[t]=s2;
    __syncthreads();
    if (t < 128){ sm[t]=fmaxf(sm[t],sm[t+128]); ss[t]+=ss[t+128]; ss2[t]+=ss2[t+128]; }
    __syncthreads();
    if (t < 64){
        mx = fmaxf(sm[t],sm[t+64]); s = ss[t]+ss[t+64]; s2 = ss2[t]+ss2[t+64];
        g_m1t[((long)b*NN+n)*64 + t] = mx;
        atomicAdd(&g_sum[t], s);
        atomicAdd(&g_sumsq[t], s2);
    }
}

__global__ void zero_stats_k(){ int t=threadIdx.x; if (t<64){ g_sum[t]=0.f; g_sumsq[t]=0.f; } }

__global__ void ec_fin_k()
{
    int t=threadIdx.x;
    if (t<64){
        float cnt = (float)((long)BB*NN*KK);
        float m = g_sum[t]/cnt;
        float var = fmaxf(g_sumsq[t]/cnt - m*m, 0.f);
        g_mean[t]=m;
        g_rstd[t]=__fdiv_rn(1.f, __fsqrt_rn(__fadd_rn(var, 1e-5f)));
    }
}

__global__ void __launch_bounds__(256) ec_norm_k(float* __restrict__ featslice,
                                                 float* __restrict__ f1t)
{
    int b = blockIdx.y, t = threadIdx.x;
    int n = blockIdx.x*4 + (t>>6), c = t & 63;
    float v = g_m1t[((long)b*NN+n)*64 + c];
    v = fmaxf(__fmul_rn(__fsub_rn(v, g_mean[c]), g_rstd[c]), 0.f);
    featslice[(long)b*128*NN + (long)c*NN + n] = v;
    if (f1t) f1t[((long)b*NN+n)*64 + c] = v;
}

// ---------------- BN stats over [B][C][N]: deterministic two-pass, fp64 ----------------
__global__ void __launch_bounds__(256) stats_mean_k(const float* __restrict__ z, int C)
{
    int c = blockIdx.x, t = threadIdx.x;
    double s = 0.0;
    for (int i=t; i<BB*NN; i+=256){
        int b = i>>11, n = i&(NN-1);
        s += (double)z[((long)b*C + c)*NN + n];
    }
    __shared__ double sd[256];
    sd[t]=s; __syncthreads();
    for (int off=128; off; off>>=1){
        if (t<off) sd[t]+=sd[t+off];
        __syncthreads();
    }
    if (t==0) g_mean[c] = (float)(sd[0] / (double)(BB*NN));
}

__global__ void __launch_bounds__(256) stats_var_k(const float* __restrict__ z, int C)
{
    int c = blockIdx.x, t = threadIdx.x;
    float m = g_mean[c];
    double s = 0.0;
    for (int i=t; i<BB*NN; i+=256){
        int b = i>>11, n = i&(NN-1);
        float d = __fsub_rn(z[((long)b*C + c)*NN + n], m);
        s += (double)__fmul_rn(d,d);
    }
    __shared__ double sd[256];
    sd[t]=s; __syncthreads();
    for (int off=128; off; off>>=1){
        if (t<off) sd[t]+=sd[t+off];
        __syncthreads();
    }
    if (t==0){
        float var = (float)(sd[0] / (double)(BB*NN));
        g_rstd[c] = __fdiv_rn(1.f, __fsqrt_rn(__fadd_rn(var, 1e-5f)));
    }
}

__global__ void bn_relu_k(const float* __restrict__ z, float* __restrict__ o, int C)
{
    long i = (long)blockIdx.x*256 + threadIdx.x;
    int c = (int)((i>>11) & (C-1));
    float v = z[i];
    o[i] = fmaxf(__fmul_rn(__fsub_rn(v, g_mean[c]), g_rstd[c]), 0.f);
}

__global__ void bn_relu_add_k(const float* __restrict__ u, const float* __restrict__ xin,
                              long xs, float* __restrict__ o)
{
    long i = (long)blockIdx.x*256 + threadIdx.x;
    long b = i/(128L*NN); long r = i - b*128L*NN;
    int c = (int)((r>>11) & 127);
    float v = fmaxf(__fmul_rn(__fsub_rn(u[i], g_mean[c]), g_rstd[c]), 0.f);
    o[b*512L*NN + r] = __fadd_rn(xin[b*xs + r], v);
}

// ---------------- flash attention pass A: rowmax + 1/rowsum ----------------
__global__ void __launch_bounds__(256) attn_rowstats_k()
{
    int b = blockIdx.y;
    int n0 = blockIdx.x*8;
    int t = threadIdx.x, w = t>>5, lane = t&31;
    __shared__ float xqs[8][33];
    __shared__ float xks[32][132];
    {
        int n = t>>5, c = t&31;
        xqs[n][c] = g_xqt[((long)b*NN + n0+n)*32 + c];
    }
    float runmax = -INFINITY, runsum = 0.f;
    const float* xkb = g_xk + (long)b*32*NN;
    for (int mt=0; mt<16; mt++){
        __syncthreads();
        for (int i=t; i<4096; i+=256){
            int c=i>>7, m=i&127;
            xks[c][m] = xkb[(long)c*NN + mt*128 + m];
        }
        __syncthreads();
        float e[4];
        #pragma unroll
        for (int j=0;j<4;j++){
            int m = lane + j*32;
            float acc = 0.f;
            #pragma unroll
            for (int c=0;c<32;c++) acc = fmaf(xqs[w][c], xks[c][m], acc);
            e[j] = acc;
        }
        float tmax = fmaxf(fmaxf(e[0],e[1]), fmaxf(e[2],e[3]));
        #pragma unroll
        for (int off=16;off;off>>=1) tmax = fmaxf(tmax, __shfl_xor_sync(0xffffffffu,tmax,off));
        float newmax = fmaxf(runmax, tmax);
        float ts = 0.f;
        #pragma unroll
        for (int j=0;j<4;j++) ts = __fadd_rn(ts, fast_exp(__fsub_rn(e[j], newmax)));
        #pragma unroll
        for (int off=16;off;off>>=1) ts = __fadd_rn(ts, __shfl_xor_sync(0xffffffffu,ts,off));
        float f = (runmax == -INFINITY) ? 0.f : fast_exp(__fsub_rn(runmax, newmax));
        runsum = __fadd_rn(__fmul_rn(runsum, f), ts);
        runmax = newmax;
    }
    if (lane == 0){
        g_rmax[(long)b*NN + n0 + w] = runmax;
        g_rinv[(long)b*NN + n0 + w] = __fdiv_rn(1.f, runsum);
    }
}

// ---------------- flash attention pass B: tb = xin - (x@attn)/(1e-6+colsum) ----------------
__global__ void __launch_bounds__(256) attn_apply_k(const float* __restrict__ xin, long xs)
{
    int b = blockIdx.y;
    int m0 = blockIdx.x*64;
    int t = threadIdx.x;
    int tx = t&15, ty = t>>4;
    __shared__ float xq_s[32][33];
    __shared__ float xk_s[32][66];
    __shared__ float w_s[32][66];
    __shared__ float x_s[128][33];
    __shared__ float cs_s[64];
    float acc[8][4];
    #pragma unroll
    for (int i=0;i<8;i++)
        #pragma unroll
        for (int j=0;j<4;j++) acc[i][j]=0.f;
    float cacc = 0.f;
    const float* xib = xin + (long)b*xs;
    const float* xkb = g_xk + (long)b*32*NN;
    const float* rmax = g_rmax + (long)b*NN;
    const float* rinv = g_rinv + (long)b*NN;

    for (int nt=0; nt<64; nt++){
        int nbase = nt*32;
        __syncthreads();
        for (int i=t;i<1024;i+=256){ int n=i>>5,c=i&31; xq_s[n][c]=g_xqt[((long)b*NN+nbase+n)*32+c]; }
        for (int i=t;i<2048;i+=256){ int c=i>>6,m=i&63; xk_s[c][m]=xkb[(long)c*NN+m0+m]; }
        for (int i=t;i<4096;i+=256){ int r=i>>5,n=i&31; x_s[r][n]=xib[(long)r*NN+nbase+n]; }
        __syncthreads();
        #pragma unroll
        for (int i2=0;i2<8;i2++){
            int lin = t + i2*256;
            int n = lin>>6, m = lin&63;
            float e=0.f;
            #pragma unroll
            for (int c=0;c<32;c++) e = fmaf(xq_s[n][c], xk_s[c][m], e);
            w_s[n][m] = __fmul_rn(fast_exp(__fsub_rn(e, rmax[nbase+n])), rinv[nbase+n]);
        }
        __syncthreads();
        if (t < 64){
            #pragma unroll 8
            for (int n=0;n<32;n++) cacc = __fadd_rn(cacc, w_s[n][t]);
        }
        #pragma unroll 4
        for (int n=0;n<32;n++){
            float rb[4];
            #pragma unroll
            for (int j=0;j<4;j++) rb[j] = w_s[n][tx*4+j];
            #pragma unroll
            for (int i=0;i<8;i++){
                float a = x_s[ty*8+i][n];
                #pragma unroll
                for (int j=0;j<4;j++) acc[i][j] = fmaf(a, rb[j], acc[i][j]);
            }
        }
    }
    if (t<64) cs_s[t] = cacc;
    __syncthreads();
    float* tbb = g_tb + (long)b*128*NN;
    #pragma unroll
    for (int i=0;i<8;i++){
        int r = ty*8+i;
        #pragma unroll
        for (int j=0;j<4;j++){
            int m = tx*4+j;
            float v = __fdiv_rn(acc[i][j], __fadd_rn(1e-6f, cs_s[m]));
            tbb[(long)r*NN + m0+m] = __fsub_rn(xib[(long)r*NN + m0+m], v);
        }
    }
}

// ---------------- head ----------------
__global__ void gmax_k()
{
    int o=blockIdx.x, b=blockIdx.y, t=threadIdx.x;
    const float* p = g_fuse + ((long)b*1024 + o)*NN;
    float m=-INFINITY;
    for (int i=t;i<NN;i+=256) m=fmaxf(m,p[i]);
    __shared__ float sm[256]; sm[t]=m; __syncthreads();
    for (int off=128;off;off>>=1){ if(t<off) sm[t]=fmaxf(sm[t],sm[t+off]); __syncthreads(); }
    if (t==0) g_gm[b*1024+o]=sm[0];
}

__global__ void c0_k(const float* __restrict__ Wc1, const float* __restrict__ bc1)
{
    int o=blockIdx.x, b=blockIdx.y, t=threadIdx.x;
    float s=0.f;
    for (int c=t; c<1024; c+=256)
        s = fmaf(Wc1[(long)o*1536 + c], g_gm[b*1024+c], s);
    __shared__ float ss[256]; ss[t]=s; __syncthreads();
    for (int off=128;off;off>>=1){ if(t<off) ss[t]=__fadd_rn(ss[t],ss[t+off]); __syncthreads(); }
    if (t==0) g_c0[b*512+o]=__fadd_rn(ss[0],bc1[o]);
}

// ---------------- host ----------------
template<typename T, size_t NSZ>
static T* SP(T (&arr)[NSZ]){ void* p=nullptr; cudaGetSymbolAddress(&p, arr); return (T*)p; }

template<int RM>
static void sgemmT(const float* A,int lda,long sA,const float* B,int ldb,long sB,
                   float* C,int ldc,long sC,int M,int Nn,int Kd,
                   const float* bias,const float* rowbias,const float* colscale,int transOut)
{
    dim3 g((Nn+TBN-1)/TBN,(M+16*RM-1)/(16*RM),BB);
    sgemm_t<RM><<<g,256>>>(A,lda,sA,B,ldb,sB,C,ldc,sC,M,Nn,Kd,bias,rowbias,colscale,transOut);
}

template<int RM>
static void bgemmT(const float* A,int lda,long sA,const float* B,int ldb,long sB,
                   float* C,int ldc,long sC,int M,int Nn,int Kd,
                   const float* bias,const float* rowbias,const float* colscale,int transOut)
{
    dim3 g(Nn/TBN, M/(16*RM), BB);
    bgemm_t<RM><<<g,256>>>(A,lda,sA,B,ldb,sB,C,ldc,sC,M,Nn,Kd,bias,rowbias,colscale,transOut);
}

extern "C" void kernel_launch(void* const* d_in, const int* in_sizes, int n_in,
                              void* d_out, int out_size)
{
    const float* x   = (const float*)d_in[0];
    const float* We1 = (const float*)d_in[1];
    const float* be1 = (const float*)d_in[2];
    const float* We2 = (const float*)d_in[3];
    const float* be2 = (const float*)d_in[4];
    const float* Wq  = (const float*)d_in[5];
    const float* Wk  = (const float*)d_in[6];
    const float* Wt  = (const float*)d_in[7];
    const float* bt  = (const float*)d_in[8];
    const float* Wf  = (const float*)d_in[9];
    const float* bf  = (const float*)d_in[10];
    const float* Wc1 = (const float*)d_in[11];
    const float* bc1 = (const float*)d_in[12];
    const float* Wc2 = (const float*)d_in[13];
    const float* bc2 = (const float*)d_in[14];
    const float* Wc3 = (const float*)d_in[15];
    const float* bc3 = (const float*)d_in[16];
    float* out = (float*)d_out;

    float* big  = SP(g_big);
    float* f1t  = SP(g_f1t);
    float* feat = SP(g_feat);
    float* cat  = SP(g_cat);
    float* xqt  = SP(g_xqt);
    float* xk   = SP(g_xk);
    float* tb   = SP(g_tb);
    float* ub   = SP(g_ub);
    float* fuse = SP(g_fuse);
    float* c0   = SP(g_c0);
    float* h1   = SP(g_h1);
    float* h2   = SP(g_h2);
    float* xt   = SP(g_xt);
    float* Wa1  = SP(g_Wa1); float* Wb1 = SP(g_Wb1);
    float* Wa2  = SP(g_Wa2); float* Wb2 = SP(g_Wb2);

    // ---- weight prep ----
    prep_w_k<<<16,256>>>(We1, We2);

    // ---- EdgeConv block 1 (C=3): fused pdist + histogram select ----
    xx1_k<<<dim3(NN/256,BB),256>>>(x);
    transpose3_k<<<dim3(NN/256,BB),256>>>(x);
    topk_sel3_k<<<dim3(NN,BB),256>>>();
    zero_stats_k<<<1,64>>>();
    ec_pass_t<3><<<dim3(NN,BB),256>>>(xt, Wa1, Wb1, be1);
    ec_fin_k<<<1,64>>>();
    ec_norm_k<<<dim3(NN/4,BB),256>>>(feat, f1t);
    xx2_k<<<dim3(NN/256,BB),256>>>();

    // ---- EdgeConv block 2 (C=64) ----
    bgemmT<8>(f1t,64,64L*NN, feat,NN,128L*NN, big,NN,(long)NN*NN, NN,NN,64, 0,0,0,0); // G2
    topk_sel_t<64><<<dim3(NN,BB),256>>>(f1t);
    zero_stats_k<<<1,64>>>();
    ec_pass_t<64><<<dim3(NN,BB),256>>>(f1t, Wa2, Wb2, be2);
    ec_fin_k<<<1,64>>>();
    ec_norm_k<<<dim3(NN/4,BB),256>>>(feat + 64L*NN, (float*)0);

    // ---- 4 SA layers (flash attention) ----
    for (int il=0; il<4; il++){
        const float* xin = (il==0)? feat : cat + (long)(il-1)*128*NN;
        long xs = (il==0)? 128L*NN : 512L*NN;
        bgemmT<2>(Wq+il*32*128,128,0, xin,NN,xs, xqt,32,32L*NN, 32,NN,128, 0,0,0,1);   // xq^T
        bgemmT<2>(Wk+il*32*128,128,0, xin,NN,xs, xk, NN,32L*NN, 32,NN,128, 0,0,0,0);   // xk
        attn_rowstats_k<<<dim3(NN/8,BB),256>>>();
        attn_apply_k<<<dim3(NN/64,BB),256>>>(xin, xs);                                 // tb = xin - xr
        bgemmT<4>(Wt+il*128*128,128,0, tb,NN,128L*NN, ub,NN,128L*NN, 128,NN,128, bt+il*128,0,0,0);
        stats_mean_k<<<128,256>>>(ub,128);
        stats_var_k<<<128,256>>>(ub,128);
        bn_relu_add_k<<<(BB*128*NN)/256,256>>>(ub, xin, xs, cat + (long)il*128*NN);
    }

    // ---- head ----
    bgemmT<8>(Wf,512,0, cat,NN,512L*NN, fuse,NN,1024L*NN, 1024,NN,512, bf,0,0,0);
    stats_mean_k<<<1024,256>>>(fuse,1024);
    stats_var_k<<<1024,256>>>(fuse,1024);
    bn_relu_k<<<(BB*1024*NN)/256,256>>>(fuse,fuse,1024);
    gmax_k<<<dim3(1024,BB),256>>>();
    c0_k<<<dim3(512,BB),256>>>(Wc1, bc1);
    bgemmT<8>(Wc1+1024,1536,0, cat,NN,512L*NN, h1,NN,512L*NN, 512,NN,512, 0,c0,0,0);
    stats_mean_k<<<512,256>>>(h1,512);
    stats_var_k<<<512,256>>>(h1,512);
    bn_relu_k<<<(BB*512*NN)/256,256>>>(h1,h1,512);
    bgemmT<4>(Wc2,512,0, h1,NN,512L*NN, h2,NN,256L*NN, 256,NN,512, bc2,0,0,0);
    stats_mean_k<<<256,256>>>(h2,256);
    stats_var_k<<<256,256>>>(h2,256);
    bn_relu_k<<<(BB*256*NN)/256,256>>>(h2,h2,256);
    sgemmT<1>(Wc3,256,0, h2,NN,256L*NN, out,NN,13L*NN, 13,NN,256, bc3,0,0,0);
}

// round 15
// speedup vs baseline: 1.2089x; 1.0071x over previous
#include <cuda_runtime.h>
#include <math.h>

#define BB 8
#define NN 2048
#define KK 32

// ---------------- scratch (device globals; no allocations) ----------------
__device__ float  g_big[BB*NN*NN];     // 134MB: G2 (knn) only
__device__ int    g_idx[BB*NN*KK];
__device__ float  g_xt [BB*NN*3];
__device__ float  g_xx [BB*NN];
__device__ float  g_Wa1[3*64],  g_Wb1[3*64];
__device__ float  g_Wa2[64*64], g_Wb2[64*64];
__device__ float  g_m1t[BB*NN*64];
__device__ float  g_f1t[BB*NN*64];
__device__ float  g_feat[BB*128*NN];
__device__ float  g_cat [BB*512*NN];
__device__ float  g_xqt [BB*NN*32];
__device__ float  g_xk  [BB*32*NN];
__device__ float  g_rmax[BB*NN];
__device__ float  g_rinv[BB*NN];
__device__ float  g_tb  [BB*128*NN];
__device__ float  g_ub  [BB*128*NN];
__device__ float  g_fuse[BB*1024*NN];
__device__ float  g_gm  [BB*1024];
__device__ float  g_c0  [BB*512];
__device__ float  g_h1  [BB*512*NN];
__device__ float  g_h2  [BB*256*NN];
__device__ float  g_sum[1024];
__device__ float  g_sumsq[1024];
__device__ float  g_mean[1024];
__device__ float  g_rstd[1024];

// ---------------- double-float helpers ----------------
__device__ __forceinline__ void twoSum(float a, float b, float& s, float& e){
    s = __fadd_rn(a,b);
    float bb = __fsub_rn(s,a);
    e = __fadd_rn(__fsub_rn(a, __fsub_rn(s,bb)), __fsub_rn(b,bb));
}
__device__ __forceinline__ void dfMac(float& hi, float& lo, float a, float b){
    float p = __fmul_rn(a,b);
    float e = fmaf(a,b,-p);
    float s, err;
    twoSum(hi, p, s, err);
    lo = __fadd_rn(lo, __fadd_rn(err, e));
    float hi2 = __fadd_rn(s, lo);
    lo = __fsub_rn(lo, __fsub_rn(hi2, s));
    hi = hi2;
}

// order-preserving float<->uint
__device__ __forceinline__ unsigned f2u(float v){
    unsigned b = __float_as_uint(v);
    return (b & 0x80000000u) ? ~b : (b | 0x80000000u);
}
__device__ __forceinline__ float u2f(unsigned u){
    unsigned b = (u & 0x80000000u) ? (u & 0x7FFFFFFFu) : ~u;
    return __uint_as_float(b);
}

// ---------------- FMA-pipe exp (no MUFU), ~2ulp, x <= 0 ----------------
__device__ __forceinline__ float fast_exp(float x){
    float z  = fmaf(x, 1.442695041f, 12582912.0f);
    float nf = __fsub_rn(z, 12582912.0f);
    int   ni = (__float_as_int(z) & 0x7FFFFF) - 4194304;
    float r  = fmaf(nf, -0.693145751953125f, x);
    r = fmaf(nf, -1.42860677e-6f, r);
    float p = 1.9875691500e-4f;
    p = fmaf(p, r, 1.3981999507e-3f);
    p = fmaf(p, r, 8.3334519073e-3f);
    p = fmaf(p, r, 4.1665795894e-2f);
    p = fmaf(p, r, 1.6666665459e-1f);
    p = fmaf(p, r, 5.0000001201e-1f);
    float e = __fadd_rn(fmaf(__fmul_rn(r,r), p, r), 1.0f);
    if (ni < -126) ni = -126;
    float sc = __int_as_float((ni + 127) << 23);
    return __fmul_rn(e, sc);
}

// ---------------- cp.async helpers ----------------
__device__ __forceinline__ void cp16(void* dst, const void* src){
    unsigned s = (unsigned)__cvta_generic_to_shared(dst);
    asm volatile("cp.async.ca.shared.global [%0], [%1], 16;" :: "r"(s), "l"(src) : "memory");
}
__device__ __forceinline__ void cp8(void* dst, const void* src){
    unsigned s = (unsigned)__cvta_generic_to_shared(dst);
    asm volatile("cp.async.ca.shared.global [%0], [%1], 8;" :: "r"(s), "l"(src) : "memory");
}
__device__ __forceinline__ void cp_commit(){ asm volatile("cp.async.commit_group;" ::: "memory"); }
template<int N>
__device__ __forceinline__ void cp_wait(){ asm volatile("cp.async.wait_group %0;" :: "n"(N) : "memory"); }

// ---------------- BIG GEMM: no bounds, cp.async double-buffered ----------------
#define TBK 16
#define TBN 128

template<int RM>
__global__ void __launch_bounds__(256) bgemm_t(
    const float* __restrict__ A, int lda, long sA,
    const float* __restrict__ Bm, int ldb, long sB,
    float* __restrict__ C, int ldc, long sC,
    int M, int Nn, int Kd,
    const float* __restrict__ bias,
    const float* __restrict__ rowbias,
    const float* __restrict__ colscale,
    int transOut, int doStats)
{
    const int TM = 16*RM;
    __shared__ float As[2][16*RM][20];
    __shared__ float Bs[2][TBK][132];
    int b = blockIdx.z;
    const float* Ab = A + (long)b*sA;
    const float* Bb = Bm + (long)b*sB;
    float* Cb = C + (long)b*sC;
    int m0 = blockIdx.y*TM, n0 = blockIdx.x*TBN;
    int tid = threadIdx.x;
    int tx = tid & 15, ty = tid >> 4;

    float acc[RM][8];
    #pragma unroll
    for (int i=0;i<RM;i++)
        #pragma unroll
        for (int j=0;j<8;j++) acc[i][j]=0.f;

    int KT = Kd / TBK;

    auto prefetch = [&](int kt, int buf){
        int k0 = kt*TBK;
        if (RM == 8){
            int row = tid >> 1, off = (tid & 1) * 8;
            const float* src = Ab + (long)(m0+row)*lda + k0 + off;
            cp16(&As[buf][row][off],   src);
            cp16(&As[buf][row][off+4], src+4);
        } else if (RM == 4){
            int row = tid >> 2, off = (tid & 3) * 4;
            cp16(&As[buf][row][off], Ab + (long)(m0+row)*lda + k0 + off);
        } else {
            int row = tid >> 3, off = (tid & 7) * 2;
            cp8(&As[buf][row][off], Ab + (long)(m0+row)*lda + k0 + off);
        }
        {
            int krow = tid >> 4, cseg = tid & 15;
            const float* src = Bb + (long)(k0+krow)*ldb + n0 + cseg*8;
            cp16(&Bs[buf][krow][cseg*8],   src);
            cp16(&Bs[buf][krow][cseg*8+4], src+4);
        }
    };

    prefetch(0, 0);
    cp_commit();

    for (int kt = 0; kt < KT; kt++){
        int buf = kt & 1;
        if (kt+1 < KT){
            prefetch(kt+1, (kt+1)&1);
            cp_commit();
            cp_wait<1>();
        } else {
            cp_wait<0>();
        }
        __syncthreads();
        #pragma unroll
        for (int kk = 0; kk < TBK; kk++){
            float ra[RM], rb[8];
            #pragma unroll
            for (int i=0;i<RM;i++) ra[i] = As[buf][ty*RM+i][kk];
            float4 b0 = *reinterpret_cast<const float4*>(&Bs[buf][kk][tx*8]);
            float4 b1 = *reinterpret_cast<const float4*>(&Bs[buf][kk][tx*8+4]);
            rb[0]=b0.x; rb[1]=b0.y; rb[2]=b0.z; rb[3]=b0.w;
            rb[4]=b1.x; rb[5]=b1.y; rb[6]=b1.z; rb[7]=b1.w;
            #pragma unroll
            for (int i=0;i<RM;i++)
                #pragma unroll
                for (int j=0;j<8;j++)
                    acc[i][j] = fmaf(ra[i], rb[j], acc[i][j]);
        }
        __syncthreads();
    }

    #pragma unroll
    for (int i=0;i<RM;i++){
        int row = m0 + ty*RM + i;
        float rb0 = 0.f;
        bool hasb = false;
        if (bias){    rb0 = __fadd_rn(rb0, bias[row]); hasb = true; }
        if (rowbias){ rb0 = __fadd_rn(rb0, rowbias[(long)b*M + row]); hasb = true; }
        float rs = 0.f, rs2 = 0.f;
        #pragma unroll
        for (int j=0;j<8;j++){
            int col = n0 + tx*8 + j;
            float v = acc[i][j];
            if (hasb) v = __fadd_rn(v, rb0);
            if (colscale) v = __fdiv_rn(v, __fadd_rn(1e-6f, colscale[(long)b*Nn + col]));
            if (!transOut) Cb[(long)row*ldc + col] = v;
            else           Cb[(long)col*ldc + row] = v;
            rs += v;
            rs2 = fmaf(v, v, rs2);
        }
        if (doStats){
            #pragma unroll
            for (int off=8; off; off>>=1){
                rs  += __shfl_down_sync(0xffffffffu, rs,  off, 16);
                rs2 += __shfl_down_sync(0xffffffffu, rs2, off, 16);
            }
            if (tx == 0){
                atomicAdd(&g_sum[row],   rs);
                atomicAdd(&g_sumsq[row], rs2);
            }
        }
    }
}

// ---------------- generic checked SGEMM (M=13 case) ----------------
template<int RM>
__global__ void __launch_bounds__(256) sgemm_t(
    const float* __restrict__ A, int lda, long sA,
    const float* __restrict__ Bm, int ldb, long sB,
    float* __restrict__ C, int ldc, long sC,
    int M, int Nn, int Kd,
    const float* __restrict__ bias,
    const float* __restrict__ rowbias,
    const float* __restrict__ colscale,
    int transOut)
{
    const int TM = 16*RM;
    __shared__ float As[TBK][16*RM+4];
    __shared__ float Bs[TBK][TBN+4];
    int b = blockIdx.z;
    const float* Ab = A + (long)b*sA;
    const float* Bb = Bm + (long)b*sB;
    float* Cb = C + (long)b*sC;
    int m0 = blockIdx.y*TM, n0 = blockIdx.x*TBN;
    int tid = threadIdx.x;
    int tx = tid & 15, ty = tid >> 4;

    float acc[RM][8];
    #pragma unroll
    for (int i=0;i<RM;i++)
        #pragma unroll
        for (int j=0;j<8;j++) acc[i][j]=0.f;

    const int TPR = 16/RM;
    int aRow  = tid / TPR;
    int aCol0 = (tid % TPR) * RM;
    int bRow  = tid >> 4;
    int bCol0 = (tid & 15) * 8;

    for (int k0 = 0; k0 < Kd; k0 += TBK) {
        #pragma unroll
        for (int j = 0; j < RM; j++) {
            int m = aRow, k = aCol0 + j;
            float v = 0.f;
            if (m0+m < M && k0+k < Kd) v = Ab[(long)(m0+m)*lda + k0+k];
            As[k][m] = v;
        }
        #pragma unroll
        for (int j = 0; j < 8; j++) {
            int k = bRow, n = bCol0 + j;
            float v = 0.f;
            if (k0+k < Kd && n0+n < Nn) v = Bb[(long)(k0+k)*ldb + n0+n];
            Bs[k][n] = v;
        }
        __syncthreads();
        #pragma unroll
        for (int kk = 0; kk < TBK; kk++) {
            float ra[RM], rb[8];
            #pragma unroll
            for (int i=0;i<RM;i++) ra[i] = As[kk][ty*RM+i];
            float4 b0 = *reinterpret_cast<const float4*>(&Bs[kk][tx*8]);
            float4 b1 = *reinterpret_cast<const float4*>(&Bs[kk][tx*8+4]);
            rb[0]=b0.x; rb[1]=b0.y; rb[2]=b0.z; rb[3]=b0.w;
            rb[4]=b1.x; rb[5]=b1.y; rb[6]=b1.z; rb[7]=b1.w;
            #pragma unroll
            for (int i=0;i<RM;i++)
                #pragma unroll
                for (int j=0;j<8;j++)
                    acc[i][j] = fmaf(ra[i], rb[j], acc[i][j]);
        }
        __syncthreads();
    }
    #pragma unroll
    for (int i=0;i<RM;i++){
        int row = m0 + ty*RM + i;
        if (row >= M) continue;
        float rb0 = 0.f;
        bool hasb = false;
        if (bias){    rb0 = __fadd_rn(rb0, bias[row]); hasb = true; }
        if (rowbias){ rb0 = __fadd_rn(rb0, rowbias[(long)b*M + row]); hasb = true; }
        #pragma unroll
        for (int j=0;j<8;j++){
            int col = n0 + tx*8 + j;
            if (col >= Nn) continue;
            float v = acc[i][j];
            if (hasb) v = __fadd_rn(v, rb0);
            if (colscale) v = __fdiv_rn(v, __fadd_rn(1e-6f, colscale[(long)b*Nn + col]));
            if (!transOut) Cb[(long)row*ldc + col] = v;
            else           Cb[(long)col*ldc + row] = v;
        }
    }
}

// ---------------- small helpers ----------------
__global__ void prep_w_k(const float* __restrict__ We1, const float* __restrict__ We2)
{
    int i = blockIdx.x*256 + threadIdx.x;
    if (i < 64*3){ int o=i/3, c=i-o*3;
        g_Wa1[c*64+o] = We1[o*6+c];
        g_Wb1[c*64+o] = We1[o*6+3+c];
    }
    if (i < 64*64){ int o=i>>6, c=i&63;
        g_Wa2[c*64+o] = We2[o*128+c];
        g_Wb2[c*64+o] = We2[o*128+64+c];
    }
}

__global__ void transpose3_k(const float* __restrict__ x)
{
    int b=blockIdx.y; int n=blockIdx.x*256+threadIdx.x;
    #pragma unroll
    for (int c=0;c<3;c++)
        g_xt[((long)b*NN+n)*3+c] = x[(long)b*3*NN + (long)c*NN + n];
}

__global__ void xx1_k(const float* __restrict__ x)
{
    int b=blockIdx.y; int n=blockIdx.x*256+threadIdx.x;
    float s=0.f;
    #pragma unroll
    for (int c=0;c<3;c++){
        float v = x[(long)b*3*NN+(long)c*NN+n];
        s = __fadd_rn(s, __fmul_rn(v,v));
    }
    g_xx[b*NN+n]=s;
}

__global__ void xx2_k()
{
    int b=blockIdx.y; int n=blockIdx.x*256+threadIdx.x;
    const float* p = g_feat + (long)b*128*NN + n;
    float s=0.f;
    #pragma unroll 8
    for (int c=0;c<64;c++){
        float v = p[(long)c*NN];
        s = __fadd_rn(s, __fmul_rn(v,v));
    }
    g_xx[b*NN+n]=s;
}

// ============ histogram threshold select + exact df re-rank ============
#define CCAP 384

__global__ void __launch_bounds__(256) topk_sel3_k()
{
    int b = blockIdx.y, n = blockIdx.x, t = threadIdx.x;
    const float* xxb = g_xx + (long)b*NN;
    __shared__ float xs3[3*NN];
    __shared__ int   hist[2048];
    __shared__ int   cs[256];
    __shared__ int   gsum[32];
    __shared__ int   s_B;
    __shared__ int   scand[CCAP];
    __shared__ int   scnt;
    __shared__ float ch[CCAP], cl[CCAP];

    for (int i=t; i<NN; i+=256){
        #pragma unroll
        for (int c=0;c<3;c++) xs3[c*NN+i] = g_xt[((long)b*NN+i)*3 + c];
    }
    for (int i=t; i<2048; i+=256) hist[i]=0;
    if (t==0) scnt = 0;
    __syncthreads();
    float c0 = xs3[n], c1 = xs3[NN+n], c2 = xs3[2*NN+n];
    float xxn = xxb[n];
    float lv[8];
    #pragma unroll
    for (int j=0;j<8;j++){
        int m = t + j*256;
        float d0 = __fsub_rn(xs3[m], c0);
        float d1 = __fsub_rn(xs3[NN+m], c1);
        float d2 = __fsub_rn(xs3[2*NN+m], c2);
        lv[j] = -fmaf(d2,d2, fmaf(d1,d1, __fmul_rn(d0,d0)));
        atomicAdd(&hist[f2u(lv[j])>>21], 1);
    }
    __syncthreads();
    {
        int s=0;
        #pragma unroll
        for (int k2=0;k2<8;k2++) s += hist[t*8+k2];
        cs[t]=s;
    }
    __syncthreads();
    if (t < 32){
        int s=0;
        #pragma unroll
        for (int k2=0;k2<8;k2++) s += cs[t*8+k2];
        gsum[t]=s;
    }
    __syncthreads();
    if (t==0){
        int run=0, g=31;
        for (; g>0; g--){ if (run+gsum[g] >= KK) break; run += gsum[g]; }
        int cch = g*8+7;
        for (; cch>0; cch--){ if (run+cs[cch] >= KK) break; run += cs[cch]; }
        int bkt = cch*8+7;
        for (; bkt>0; bkt--){ if (run+hist[bkt] >= KK) break; run += hist[bkt]; }
        s_B = bkt;
    }
    __syncthreads();
    float Tf = u2f((unsigned)s_B << 21);
    #pragma unroll
    for (int j=0;j<8;j++){
        int m = t + j*256;
        float marg = fmaf(2e-4f, xxn + xxb[m], 1e-6f);
        if (lv[j] >= __fsub_rn(Tf, marg)){
            int p = atomicAdd(&scnt, 1);
            if (p < CCAP) scand[p] = m;
        }
    }
    __syncthreads();
    int cnt = scnt < CCAP ? scnt : CCAP;

    if (t < cnt){
        int m = scand[t];
        float hi=0.f, lo=0.f;
        #pragma unroll
        for (int c=0;c<3;c++){
            float d = __fsub_rn(xs3[c*NN+m], xs3[c*NN+n]);
            dfMac(hi, lo, d, d);
        }
        ch[t]=hi; cl[t]=lo;
    }
    __syncthreads();
    if (t < cnt){
        int   mi = scand[t];
        float hi = ch[t], li = cl[t];
        int r = 0;
        for (int j=0;j<cnt;j++){
            float hj = ch[j], lj = cl[j];
            int   mj = scand[j];
            bool less = (hj < hi) || (hj == hi && (lj < li || (lj == li && mj < mi)));
            r += less;
        }
        if (r < KK) g_idx[((long)b*NN+n)*KK + r] = mi;
    }
}

template<int C>
__global__ void __launch_bounds__(256) topk_sel_t(const float* __restrict__ src)
{
    int b = blockIdx.y, n = blockIdx.x, t = threadIdx.x;
    const float* row = g_big + ((long)b*NN + n)*NN;
    const float* xxb = g_xx + (long)b*NN;
    __shared__ int   hist[2048];
    __shared__ int   cs[256];
    __shared__ int   gsum[32];
    __shared__ int   s_B;
    __shared__ int   scand[CCAP];
    __shared__ int   scnt;
    __shared__ float ch[CCAP], cl[CCAP];
    __shared__ float cen[C];

    for (int i=t; i<2048; i+=256) hist[i]=0;
    if (t==0) scnt = 0;
    if (t < C) cen[t] = src[((long)b*NN+n)*C + t];
    __syncthreads();
    float xxn = xxb[n];
    float lv[8];
    #pragma unroll
    for (int j=0;j<8;j++){
        int m = t + j*256;
        lv[j] = 2.f*row[m] - xxn - xxb[m];
        atomicAdd(&hist[f2u(lv[j])>>21], 1);
    }
    __syncthreads();
    {
        int s=0;
        #pragma unroll
        for (int k2=0;k2<8;k2++) s += hist[t*8+k2];
        cs[t]=s;
    }
    __syncthreads();
    if (t < 32){
        int s=0;
        #pragma unroll
        for (int k2=0;k2<8;k2++) s += cs[t*8+k2];
        gsum[t]=s;
    }
    __syncthreads();
    if (t==0){
        int run=0, g=31;
        for (; g>0; g--){ if (run+gsum[g] >= KK) break; run += gsum[g]; }
        int cch = g*8+7;
        for (; cch>0; cch--){ if (run+cs[cch] >= KK) break; run += cs[cch]; }
        int bkt = cch*8+7;
        for (; bkt>0; bkt--){ if (run+hist[bkt] >= KK) break; run += hist[bkt]; }
        s_B = bkt;
    }
    __syncthreads();
    float Tf = u2f((unsigned)s_B << 21);
    #pragma unroll
    for (int j=0;j<8;j++){
        int m = t + j*256;
        float marg = fmaf(2e-4f, xxn + xxb[m], 1e-6f);
        if (lv[j] >= __fsub_rn(Tf, marg)){
            int p = atomicAdd(&scnt, 1);
            if (p < CCAP) scand[p] = m;
        }
    }
    __syncthreads();
    int cnt = scnt < CCAP ? scnt : CCAP;

    if (t < cnt){
        int m = scand[t];
        const float* fm = src + ((long)b*NN+m)*C;
        float hi=0.f, lo=0.f;
        #pragma unroll 4
        for (int c=0;c<C;c++){
            float d = __fsub_rn(fm[c], cen[c]);
            dfMac(hi, lo, d, d);
        }
        ch[t]=hi; cl[t]=lo;
    }
    __syncthreads();
    if (t < cnt){
        int   mi = scand[t];
        float hi = ch[t], li = cl[t];
        int r = 0;
        for (int j=0;j<cnt;j++){
            float hj = ch[j], lj = cl[j];
            int   mj = scand[j];
            bool less = (hj < hi) || (hj == hi && (lj < li || (lj == li && mj < mi)));
            r += less;
        }
        if (r < KK) g_idx[((long)b*NN+n)*KK + r] = mi;
    }
}

// ---------------- EdgeConv: fused e + max-over-k + one-pass stats ----------------
template<int C>
__global__ void __launch_bounds__(256) ec_pass_t(
    const float* __restrict__ src,
    const float* __restrict__ Wa,
    const float* __restrict__ Wb,
    const float* __restrict__ be)
{
    int b = blockIdx.y, n = blockIdx.x, t = threadIdx.x;
    __shared__ int   sidx[KK];
    __shared__ float cen[C];
    __shared__ float Was[C*64];
    __shared__ float Wbs[C*64];
    __shared__ float dr[KK][C + (C==64 ? 1 : 0)];
    __shared__ float t1s[64];
    __shared__ float sm[256], ss[256], ss2[256];

    const float* sb = src + (long)b*NN*C;
    if (t < KK) sidx[t] = g_idx[((long)b*NN+n)*KK + t];
    if (t < C)  cen[t] = sb[(long)n*C + t];
    for (int i=t; i<C*64; i+=256){ Was[i] = Wa[i]; Wbs[i] = Wb[i]; }
    __syncthreads();

    if (t < 64){
        float a = 0.f;
        #pragma unroll
        for (int c=0;c<C;c++) a = fmaf(Wbs[c*64+t], cen[c], a);
        t1s[t] = __fadd_rn(a, be[t]);
    }
    for (int i=t; i<KK*C; i+=256){
        int k = i/C, c = i - k*C;
        dr[k][c] = __fsub_rn(sb[(long)sidx[k]*C + c], cen[c]);
    }
    __syncthreads();

    int o = t & 63, kg = t >> 6;
    float t1 = t1s[o];
    float mx = -INFINITY, s = 0.f, s2 = 0.f;
    #pragma unroll
    for (int j=0;j<8;j++){
        int k = kg*8 + j;
        float acc = 0.f;
        #pragma unroll
        for (int c=0;c<C;c++) acc = fmaf(Was[c*64+o], dr[k][c], acc);
        acc = __fadd_rn(acc, t1);
        mx = fmaxf(mx, acc);
        s += acc;
        s2 = fmaf(acc, acc, s2);
    }
    sm[t]=mx; ss[t]=s; ss2[t]=s2;
    __syncthreads();
    if (t < 128){ sm[t]=fmaxf(sm[t],sm[t+128]); ss[t]+=ss[t+128]; ss2[t]+=ss2[t+128]; }
    __syncthreads();
    if (t < 64){
        mx = fmaxf(sm[t],sm[t+64]); s = ss[t]+ss[t+64]; s2 = ss2[t]+ss2[t+64];
        g_m1t[((long)b*NN+n)*64 + t] = mx;
        atomicAdd(&g_sum[t], s);
        atomicAdd(&g_sumsq[t], s2);
    }
}

__global__ void zero_stats_c(int C){ int t=blockIdx.x*256+threadIdx.x; if (t<C){ g_sum[t]=0.f; g_sumsq[t]=0.f; } }

// finalize mean/rstd for C channels; count elements per channel = cnt
__global__ void stats_fin_c(int C, float cnt)
{
    int t = blockIdx.x*256 + threadIdx.x;
    if (t < C){
        float m = g_sum[t]/cnt;
        float var = fmaxf(g_sumsq[t]/cnt - m*m, 0.f);
        g_mean[t]=m;
        g_rstd[t]=__fdiv_rn(1.f, __fsqrt_rn(__fadd_rn(var, 1e-5f)));
    }
}

__global__ void __launch_bounds__(256) ec_norm_k(float* __restrict__ featslice,
                                                 float* __restrict__ f1t)
{
    int b = blockIdx.y, t = threadIdx.x;
    int n = blockIdx.x*4 + (t>>6), c = t & 63;
    float v = g_m1t[((long)b*NN+n)*64 + c];
    v = fmaxf(__fmul_rn(__fsub_rn(v, g_mean[c]), g_rstd[c]), 0.f);
    featslice[(long)b*128*NN + (long)c*NN + n] = v;
    if (f1t) f1t[((long)b*NN+n)*64 + c] = v;
}

__global__ void bn_relu_k(const float* __restrict__ z, float* __restrict__ o, int C)
{
    long i = (long)blockIdx.x*256 + threadIdx.x;
    int c = (int)((i>>11) & (C-1));
    float v = z[i];
    o[i] = fmaxf(__fmul_rn(__fsub_rn(v, g_mean[c]), g_rstd[c]), 0.f);
}

// fuse: bn+relu in-place on one (b,o) row + row max -> g_gm
__global__ void __launch_bounds__(256) bn_relu_gmax_k()
{
    int o = blockIdx.x, b = blockIdx.y, t = threadIdx.x;
    float* p = g_fuse + ((long)b*1024 + o)*NN;
    float mean = g_mean[o], rstd = g_rstd[o];
    float mx = -INFINITY;
    #pragma unroll
    for (int j=0;j<8;j++){
        int i = t + j*256;
        float v = fmaxf(__fmul_rn(__fsub_rn(p[i], mean), rstd), 0.f);
        p[i] = v;
        mx = fmaxf(mx, v);
    }
    __shared__ float sm[256];
    sm[t]=mx; __syncthreads();
    for (int off=128;off;off>>=1){ if(t<off) sm[t]=fmaxf(sm[t],sm[t+off]); __syncthreads(); }
    if (t==0) g_gm[b*1024+o]=sm[0];
}

__global__ void bn_relu_add_k(const float* __restrict__ u, const float* __restrict__ xin,
                              long xs, float* __restrict__ o)
{
    long i = (long)blockIdx.x*256 + threadIdx.x;
    long b = i/(128L*NN); long r = i - b*128L*NN;
    int c = (int)((r>>11) & 127);
    float v = fmaxf(__fmul_rn(__fsub_rn(u[i], g_mean[c]), g_rstd[c]), 0.f);
    o[b*512L*NN + r] = __fadd_rn(xin[b*xs + r], v);
}

// ---------------- flash attention pass A: rowmax + 1/rowsum ----------------
__global__ void __launch_bounds__(256) attn_rowstats_k()
{
    int b = blockIdx.y;
    int n0 = blockIdx.x*8;
    int t = threadIdx.x, w = t>>5, lane = t&31;
    __shared__ float xqs[8][33];
    __shared__ float xks[32][132];
    {
        int n = t>>5, c = t&31;
        xqs[n][c] = g_xqt[((long)b*NN + n0+n)*32 + c];
    }
    float runmax = -INFINITY, runsum = 0.f;
    const float* xkb = g_xk + (long)b*32*NN;
    for (int mt=0; mt<16; mt++){
        __syncthreads();
        for (int i=t; i<4096; i+=256){
            int c=i>>7, m=i&127;
            xks[c][m] = xkb[(long)c*NN + mt*128 + m];
        }
        __syncthreads();
        float e[4];
        #pragma unroll
        for (int j=0;j<4;j++){
            int m = lane + j*32;
            float acc = 0.f;
            #pragma unroll
            for (int c=0;c<32;c++) acc = fmaf(xqs[w][c], xks[c][m], acc);
            e[j] = acc;
        }
        float tmax = fmaxf(fmaxf(e[0],e[1]), fmaxf(e[2],e[3]));
        #pragma unroll
        for (int off=16;off;off>>=1) tmax = fmaxf(tmax, __shfl_xor_sync(0xffffffffu,tmax,off));
        float newmax = fmaxf(runmax, tmax);
        float ts = 0.f;
        #pragma unroll
        for (int j=0;j<4;j++) ts = __fadd_rn(ts, fast_exp(__fsub_rn(e[j], newmax)));
        #pragma unroll
        for (int off=16;off;off>>=1) ts = __fadd_rn(ts, __shfl_xor_sync(0xffffffffu,ts,off));
        float f = (runmax == -INFINITY) ? 0.f : fast_exp(__fsub_rn(runmax, newmax));
        runsum = __fadd_rn(__fmul_rn(runsum, f), ts);
        runmax = newmax;
    }
    if (lane == 0){
        g_rmax[(long)b*NN + n0 + w] = runmax;
        g_rinv[(long)b*NN + n0 + w] = __fdiv_rn(1.f, runsum);
    }
}

// ---------------- flash attention pass B: tb = xin - (x@attn)/(1e-6+colsum) ----------------
__global__ void __launch_bounds__(256) attn_apply_k(const float* __restrict__ xin, long xs)
{
    int b = blockIdx.y;
    int m0 = blockIdx.x*64;
    int t = threadIdx.x;
    int tx = t&15, ty = t>>4;
    __shared__ float xq_s[32][33];
    __shared__ float xk_s[32][66];
    __shared__ float w_s[32][66];
    __shared__ float x_s[128][33];
    __shared__ float cs_s[64];
    float acc[8][4];
    #pragma unroll
    for (int i=0;i<8;i++)
        #pragma unroll
        for (int j=0;j<4;j++) acc[i][j]=0.f;
    float cacc = 0.f;
    const float* xib = xin + (long)b*xs;
    const float* xkb = g_xk + (long)b*32*NN;
    const float* rmax = g_rmax + (long)b*NN;
    const float* rinv = g_rinv + (long)b*NN;

    for (int nt=0; nt<64; nt++){
        int nbase = nt*32;
        __syncthreads();
        for (int i=t;i<1024;i+=256){ int n=i>>5,c=i&31; xq_s[n][c]=g_xqt[((long)b*NN+nbase+n)*32+c]; }
        for (int i=t;i<2048;i+=256){ int c=i>>6,m=i&63; xk_s[c][m]=xkb[(long)c*NN+m0+m]; }
        for (int i=t;i<4096;i+=256){ int r=i>>5,n=i&31; x_s[r][n]=xib[(long)r*NN+nbase+n]; }
        __syncthreads();
        #pragma unroll
        for (int i2=0;i2<8;i2++){
            int lin = t + i2*256;
            int n = lin>>6, m = lin&63;
            float e=0.f;
            #pragma unroll
            for (int c=0;c<32;c++) e = fmaf(xq_s[n][c], xk_s[c][m], e);
            w_s[n][m] = __fmul_rn(fast_exp(__fsub_rn(e, rmax[nbase+n])), rinv[nbase+n]);
        }
        __syncthreads();
        if (t < 64){
            #pragma unroll 8
            for (int n=0;n<32;n++) cacc = __fadd_rn(cacc, w_s[n][t]);
        }
        #pragma unroll 4
        for (int n=0;n<32;n++){
            float rb[4];
            #pragma unroll
            for (int j=0;j<4;j++) rb[j] = w_s[n][tx*4+j];
            #pragma unroll
            for (int i=0;i<8;i++){
                float a = x_s[ty*8+i][n];
                #pragma unroll
                for (int j=0;j<4;j++) acc[i][j] = fmaf(a, rb[j], acc[i][j]);
            }
        }
    }
    if (t<64) cs_s[t] = cacc;
    __syncthreads();
    float* tbb = g_tb + (long)b*128*NN;
    #pragma unroll
    for (int i=0;i<8;i++){
        int r = ty*8+i;
        #pragma unroll
        for (int j=0;j<4;j++){
            int m = tx*4+j;
            float v = __fdiv_rn(acc[i][j], __fadd_rn(1e-6f, cs_s[m]));
            tbb[(long)r*NN + m0+m] = __fsub_rn(xib[(long)r*NN + m0+m], v);
        }
    }
}

// ---------------- head ----------------
__global__ void c0_k(const float* __restrict__ Wc1, const float* __restrict__ bc1)
{
    int o=blockIdx.x, b=blockIdx.y, t=threadIdx.x;
    float s=0.f;
    for (int c=t; c<1024; c+=256)
        s = fmaf(Wc1[(long)o*1536 + c], g_gm[b*1024+c], s);
    __shared__ float ss[256]; ss[t]=s; __syncthreads();
    for (int off=128;off;off>>=1){ if(t<off) ss[t]=__fadd_rn(ss[t],ss[t+off]); __syncthreads(); }
    if (t==0) g_c0[b*512+o]=__fadd_rn(ss[0],bc1[o]);
}

// ---------------- host ----------------
template<typename T, size_t NSZ>
static T* SP(T (&arr)[NSZ]){ void* p=nullptr; cudaGetSymbolAddress(&p, arr); return (T*)p; }

template<int RM>
static void sgemmT(const float* A,int lda,long sA,const float* B,int ldb,long sB,
                   float* C,int ldc,long sC,int M,int Nn,int Kd,
                   const float* bias,const float* rowbias,const float* colscale,int transOut)
{
    dim3 g((Nn+TBN-1)/TBN,(M+16*RM-1)/(16*RM),BB);
    sgemm_t<RM><<<g,256>>>(A,lda,sA,B,ldb,sB,C,ldc,sC,M,Nn,Kd,bias,rowbias,colscale,transOut);
}

template<int RM>
static void bgemmT(const float* A,int lda,long sA,const float* B,int ldb,long sB,
                   float* C,int ldc,long sC,int M,int Nn,int Kd,
                   const float* bias,const float* rowbias,const float* colscale,int transOut,
                   int doStats=0)
{
    dim3 g(Nn/TBN, M/(16*RM), BB);
    bgemm_t<RM><<<g,256>>>(A,lda,sA,B,ldb,sB,C,ldc,sC,M,Nn,Kd,bias,rowbias,colscale,transOut,doStats);
}

extern "C" void kernel_launch(void* const* d_in, const int* in_sizes, int n_in,
                              void* d_out, int out_size)
{
    const float* x   = (const float*)d_in[0];
    const float* We1 = (const float*)d_in[1];
    const float* be1 = (const float*)d_in[2];
    const float* We2 = (const float*)d_in[3];
    const float* be2 = (const float*)d_in[4];
    const float* Wq  = (const float*)d_in[5];
    const float* Wk  = (const float*)d_in[6];
    const float* Wt  = (const float*)d_in[7];
    const float* bt  = (const float*)d_in[8];
    const float* Wf  = (const float*)d_in[9];
    const float* bf  = (const float*)d_in[10];
    const float* Wc1 = (const float*)d_in[11];
    const float* bc1 = (const float*)d_in[12];
    const float* Wc2 = (const float*)d_in[13];
    const float* bc2 = (const float*)d_in[14];
    const float* Wc3 = (const float*)d_in[15];
    const float* bc3 = (const float*)d_in[16];
    float* out = (float*)d_out;

    float* big  = SP(g_big);
    float* f1t  = SP(g_f1t);
    float* feat = SP(g_feat);
    float* cat  = SP(g_cat);
    float* xqt  = SP(g_xqt);
    float* xk   = SP(g_xk);
    float* tb   = SP(g_tb);
    float* ub   = SP(g_ub);
    float* fuse = SP(g_fuse);
    float* c0   = SP(g_c0);
    float* h1   = SP(g_h1);
    float* h2   = SP(g_h2);
    float* xt   = SP(g_xt);
    float* Wa1  = SP(g_Wa1); float* Wb1 = SP(g_Wb1);
    float* Wa2  = SP(g_Wa2); float* Wb2 = SP(g_Wb2);
    const float cnt = (float)(BB*NN);

    // ---- weight prep ----
    prep_w_k<<<16,256>>>(We1, We2);

    // ---- EdgeConv block 1 (C=3) ----
    xx1_k<<<dim3(NN/256,BB),256>>>(x);
    transpose3_k<<<dim3(NN/256,BB),256>>>(x);
    topk_sel3_k<<<dim3(NN,BB),256>>>();
    zero_stats_c<<<4,256>>>(64);
    ec_pass_t<3><<<dim3(NN,BB),256>>>(xt, Wa1, Wb1, be1);
    stats_fin_c<<<4,256>>>(64, (float)((long)BB*NN*KK));
    ec_norm_k<<<dim3(NN/4,BB),256>>>(feat, f1t);
    xx2_k<<<dim3(NN/256,BB),256>>>();

    // ---- EdgeConv block 2 (C=64) ----
    bgemmT<8>(f1t,64,64L*NN, feat,NN,128L*NN, big,NN,(long)NN*NN, NN,NN,64, 0,0,0,0); // G2
    topk_sel_t<64><<<dim3(NN,BB),256>>>(f1t);
    zero_stats_c<<<4,256>>>(64);
    ec_pass_t<64><<<dim3(NN,BB),256>>>(f1t, Wa2, Wb2, be2);
    stats_fin_c<<<4,256>>>(64, (float)((long)BB*NN*KK));
    ec_norm_k<<<dim3(NN/4,BB),256>>>(feat + 64L*NN, (float*)0);

    // ---- 4 SA layers (flash attention) ----
    for (int il=0; il<4; il++){
        const float* xin = (il==0)? feat : cat + (long)(il-1)*128*NN;
        long xs = (il==0)? 128L*NN : 512L*NN;
        bgemmT<2>(Wq+il*32*128,128,0, xin,NN,xs, xqt,32,32L*NN, 32,NN,128, 0,0,0,1);   // xq^T
        bgemmT<2>(Wk+il*32*128,128,0, xin,NN,xs, xk, NN,32L*NN, 32,NN,128, 0,0,0,0);   // xk
        attn_rowstats_k<<<dim3(NN/8,BB),256>>>();
        attn_apply_k<<<dim3(NN/64,BB),256>>>(xin, xs);                                 // tb = xin - xr
        zero_stats_c<<<4,256>>>(128);
        bgemmT<4>(Wt+il*128*128,128,0, tb,NN,128L*NN, ub,NN,128L*NN, 128,NN,128, bt+il*128,0,0,0, 1);
        stats_fin_c<<<4,256>>>(128, cnt);
        bn_relu_add_k<<<(BB*128*NN)/256,256>>>(ub, xin, xs, cat + (long)il*128*NN);
    }

    // ---- head ----
    zero_stats_c<<<4,256>>>(1024);
    bgemmT<8>(Wf,512,0, cat,NN,512L*NN, fuse,NN,1024L*NN, 1024,NN,512, bf,0,0,0, 1);
    stats_fin_c<<<4,256>>>(1024, cnt);
    bn_relu_gmax_k<<<dim3(1024,BB),256>>>();
    c0_k<<<dim3(512,BB),256>>>(Wc1, bc1);
    zero_stats_c<<<4,256>>>(512);
    bgemmT<8>(Wc1+1024,1536,0, cat,NN,512L*NN, h1,NN,512L*NN, 512,NN,512, 0,c0,0,0, 1);
    stats_fin_c<<<4,256>>>(512, cnt);
    bn_relu_k<<<(BB*512*NN)/256,256>>>(h1,h1,512);
    zero_stats_c<<<4,256>>>(256);
    bgemmT<4>(Wc2,512,0, h1,NN,512L*NN, h2,NN,256L*NN, 256,NN,512, bc2,0,0,0, 1);
    stats_fin_c<<<4,256>>>(256, cnt);
    bn_relu_k<<<(BB*256*NN)/256,256>>>(h2,h2,256);
    sgemmT<1>(Wc3,256,0, h2,NN,256L*NN, out,NN,13L*NN, 13,NN,256, bc3,0,0,0);
}